// round 9
// baseline (speedup 1.0000x reference)
#include <cuda_runtime.h>
#include <math.h>
#include <stdint.h>

// Problem constants
#define BSZ   64
#define NTOK  1024
#define MCH   64
#define DCH   256       // 4*M
#define PDIM  64
#define RTOT  (BSZ*NTOK)   // 65536
#define HMAX  360
#define HPADMAX 384
#define EPSF  1e-5f
#define NBLK2 (RTOT/32)    // 2048 reglin blocks

// -------- scratch (static __device__ globals) --------
__device__ __align__(16) float g_h[(size_t)RTOT*DCH];
__device__ __align__(16) float g_y[(size_t)RTOT*DCH];
__device__ __align__(16) float g_q[(size_t)BSZ*HMAX*NTOK];
__device__ __align__(16) float g_kv[(size_t)BSZ*HMAX*NTOK];
__device__ __align__(16) float2 g_Ff[HMAX*NTOK];
// fragment-packed concatenated weights [Q | KV-interleaved]: (b0h,b0l,b1h,b1l)
__device__ __align__(16) float g_WcF[32][3*HPADMAX/8][32][4];
__device__ __align__(16) float g_WoF[HPADMAX/8][32][32][4];
__device__ float g_part0[MCH*NBLK2];
__device__ float g_part1[MCH*NBLK2];
__device__ float g_scale0[MCH];
__device__ float g_scale1[MCH];

// ---------------------------------------------------------------------------
__device__ __forceinline__ void mma_tf32(float* c, const uint32_t* a, const uint32_t* b)
{
    asm volatile(
        "mma.sync.aligned.m16n8k8.row.col.f32.tf32.tf32.f32 "
        "{%0,%1,%2,%3}, {%4,%5,%6,%7}, {%8,%9}, {%0,%1,%2,%3};\n"
        : "+f"(c[0]), "+f"(c[1]), "+f"(c[2]), "+f"(c[3])
        : "r"(a[0]), "r"(a[1]), "r"(a[2]), "r"(a[3]), "r"(b[0]), "r"(b[1]));
}

__device__ __forceinline__ float tf32_rna_f(float x)
{
    uint32_t r;
    asm("cvt.rna.tf32.f32 %0, %1;" : "=r"(r) : "f"(x));
    return __uint_as_float(r);
}
__device__ __forceinline__ uint32_t rna_bits(float x)
{
    uint32_t r;
    asm("cvt.rna.tf32.f32 %0, %1;" : "=r"(r) : "f"(x));
    return r;
}

__device__ __forceinline__ uint32_t sAddr(const void* p)
{
    return (uint32_t)__cvta_generic_to_shared(p);
}
__device__ __forceinline__ void cp16(uint32_t dst, const void* src)
{
    asm volatile("cp.async.cg.shared.global [%0], [%1], 16;\n" :: "r"(dst), "l"(src));
}
#define CP_COMMIT() asm volatile("cp.async.commit_group;\n")
#define CP_WAIT2()  asm volatile("cp.async.wait_group 2;\n")
#define CP_WAIT0()  asm volatile("cp.async.wait_group 0;\n")

__device__ __forceinline__ float2 cmul(float2 a, float2 b)
{ return make_float2(a.x*b.x - a.y*b.y, a.x*b.y + a.y*b.x); }
__device__ __forceinline__ float2 cadd(float2 a, float2 b){ return make_float2(a.x+b.x, a.y+b.y); }
__device__ __forceinline__ float2 csub(float2 a, float2 b){ return make_float2(a.x-b.x, a.y-b.y); }

// ---------------------------------------------------------------------------
// init h
// ---------------------------------------------------------------------------
__global__ void init_h_kernel(const float* __restrict__ x,
                              const float* __restrict__ tok_emb,
                              const float* __restrict__ Wf,
                              const float* __restrict__ wv)
{
    int n = blockIdx.x;
    int tid = threadIdx.x;   // 256
    __shared__ float f[PDIM];
    __shared__ float s0[MCH];
    if (tid < PDIM) {
        int p = tid;
        int j2 = p & ~1;
        float div = expf(-logf(10000.0f) * (float)j2 / (float)PDIM);
        float ang = (float)n * div;
        float pe = (p & 1) ? cosf(ang) : sinf(ang);
        int tt = (n == NTOK - 1) ? 2 : (n & 1);
        f[p] = pe + tok_emb[tt * PDIM + p];
    }
    __syncthreads();
    if (tid < MCH) {
        float acc = 0.f;
        #pragma unroll 8
        for (int p = 0; p < PDIM; p++) acc += f[p] * Wf[p * MCH + tid];
        s0[tid] = acc;
    }
    __syncthreads();
    int m = tid >> 2, r = tid & 3;
    float wvm = wv[m];
    float sv = s0[m];
    for (int b = 0; b < BSZ; b++) {
        float val;
        if (r == 0) val = sv;
        else        val = x[((size_t)b * NTOK + n) * 3 + (r - 1)] * wvm;
        g_h[((size_t)b * NTOK + n) * DCH + tid] = val;
    }
}

// ---------------------------------------------------------------------------
// weight pre-split. Column map over 3*HP:
//   c < HP          -> Wq column c
//   c >= HP         -> j=c-HP; h=j>>1; even j -> Wk[h], odd j -> Wv[h]
// ---------------------------------------------------------------------------
template<int HP>
__global__ void presplit_cat(const float* __restrict__ Wq,
                             const float* __restrict__ Wk,
                             const float* __restrict__ Wv2, int H)
{
    int idx = blockIdx.x * 256 + threadIdx.x;   // over 256 * 3*HP
    int k = idx / (3 * HP), c = idx % (3 * HP);
    const float* W;
    int h;
    if (c < HP) { W = Wq; h = c; }
    else {
        int j = c - HP;
        h = j >> 1;
        W = (j & 1) ? Wv2 : Wk;
    }
    int kb = k >> 3, kk = k & 7;
    int t = kk & 3, pos = kk >> 2;
    int cb = c >> 3, lane = (c & 7) * 4 + t;
    float w = (h < H) ? W[(size_t)k * H + h] : 0.f;
    float hi = tf32_rna_f(w);
    g_WcF[kb][cb][lane][pos * 2]     = hi;
    g_WcF[kb][cb][lane][pos * 2 + 1] = w - hi;
}

__global__ void presplit_wo(const float* __restrict__ Wo, int H)
{
    int idx = blockIdx.x * 256 + threadIdx.x;   // over HPADMAX*256
    int k = idx >> 8, n = idx & 255;
    int kb = k >> 3, kk = k & 7;
    int t = kk & 3, pos = kk >> 2;
    int cb = n >> 3, lane = (n & 7) * 4 + t;
    float w = (k < H) ? Wo[(size_t)k * DCH + n] : 0.f;
    float hi = tf32_rna_f(w);
    g_WoF[kb][cb][lane][pos * 2]     = hi;
    g_WoF[kb][cb][lane][pos * 2 + 1] = w - hi;
}

// ---------------------------------------------------------------------------
// Merged qkv GEMM: C[R, 3*HP] = A[R,256] @ Wcat. Tile 128x128, kstep 8,
// 4-stage cp.async ring (distance 3), loads issued before MMAs each step.
// Q-region tiles write q; KV-region tiles write k*v directly.
// ---------------------------------------------------------------------------
template<int HP>
__global__ void __launch_bounds__(256, 2) gemm_in(int H)
{
    __shared__ __align__(16) float shA[4][128 * 12];
    __shared__ __align__(16) float shB[4][16 * 32 * 4];

    int tid = threadIdx.x;
    int row0 = blockIdx.y * 128;
    int col0 = blockIdx.x * 128;        // over 3*HP
    int b = row0 >> 10;
    int nbase = row0 & (NTOK - 1);
    int cb0 = col0 >> 3;

    int wid = tid >> 5, lane = tid & 31;
    int g = lane >> 2, t = lane & 3;
    int wr = wid >> 2, wc = wid & 3;

    float acc[4][4][4] = {};

    int ar = tid >> 1, ahalf = tid & 1;
    const float* aSrc = &g_h[(size_t)(row0 + ar) * DCH + ahalf * 4];

    #define IN_LOAD(kb, st)                                                   \
    {                                                                         \
        cp16(sAddr(&shA[st][ar * 12 + ahalf * 4]), aSrc + (kb) * 8);          \
        _Pragma("unroll")                                                     \
        for (int i = 0; i < 2; i++) {                                         \
            int c = i * 256 + tid;                                            \
            int cb = c >> 5, ln = c & 31;                                     \
            cp16(sAddr(&shB[st][(cb * 32 + ln) * 4]),                         \
                 &g_WcF[kb][cb0 + cb][ln][0]);                                \
        }                                                                     \
        CP_COMMIT();                                                          \
    }

    IN_LOAD(0, 0);
    IN_LOAD(1, 1);
    IN_LOAD(2, 2);

    for (int kb = 0; kb < 32; kb++) {
        if (kb == 31) { CP_WAIT0(); } else { CP_WAIT2(); }
        __syncthreads();
        if (kb + 3 < 32) {
            int kn = kb + 3;
            IN_LOAD(kn, kn & 3);
        }
        int st = kb & 3;
        const float* A = shA[st];
        const float* B = shB[st];

        uint32_t ah[4][4];
        #pragma unroll
        for (int mf = 0; mf < 4; mf++) {
            int rb = wr * 64 + mf * 16;
            ah[mf][0] = rna_bits(A[(rb + g)     * 12 + t]);
            ah[mf][1] = rna_bits(A[(rb + g + 8) * 12 + t]);
            ah[mf][2] = rna_bits(A[(rb + g)     * 12 + t + 4]);
            ah[mf][3] = rna_bits(A[(rb + g + 8) * 12 + t + 4]);
        }
        #pragma unroll
        for (int nf = 0; nf < 4; nf++) {
            int cb = wc * 4 + nf;
            float4 bf = *(const float4*)&B[(cb * 32 + lane) * 4];
            uint32_t bh[2] = {__float_as_uint(bf.x), __float_as_uint(bf.z)};
            uint32_t bl[2] = {__float_as_uint(bf.y), __float_as_uint(bf.w)};
            #pragma unroll
            for (int mf = 0; mf < 4; mf++) {
                mma_tf32(acc[mf][nf], ah[mf], bh);
                mma_tf32(acc[mf][nf], ah[mf], bl);
            }
        }
    }
    #undef IN_LOAD

    if (col0 < HP) {
        // Q region (tiles never straddle: HP % 128 == 0)
        #pragma unroll
        for (int mf = 0; mf < 4; mf++) {
            #pragma unroll
            for (int nf = 0; nf < 4; nf++) {
                #pragma unroll
                for (int cc = 0; cc < 2; cc++) {
                    int col = col0 + wc * 32 + nf * 8 + t * 2 + cc;
                    if (col < H) {
                        size_t base = ((size_t)b * H + col) * NTOK + nbase + wr * 64 + mf * 16 + g;
                        g_q[base]     = acc[mf][nf][cc];
                        g_q[base + 8] = acc[mf][nf][cc + 2];
                    }
                }
            }
        }
    } else {
        // KV region: thread's two adjacent cols are (k_h, v_h) of same h
        #pragma unroll
        for (int mf = 0; mf < 4; mf++) {
            #pragma unroll
            for (int nf = 0; nf < 4; nf++) {
                int h = ((col0 - HP) >> 1) + wc * 16 + nf * 4 + t;
                if (h < H) {
                    size_t base = ((size_t)b * H + h) * NTOK + nbase + wr * 64 + mf * 16 + g;
                    g_kv[base]     = acc[mf][nf][0] * acc[mf][nf][1];
                    g_kv[base + 8] = acc[mf][nf][2] * acc[mf][nf][3];
                }
            }
        }
    }
}

// ---------------------------------------------------------------------------
// Wo GEMM + residual: g_h[R,256] += G[R,H] @ Wo[H,256].
// Tile 128x128, kstep 8, 4-stage ring (distance 3), loads before MMAs.
// ---------------------------------------------------------------------------
__global__ void __launch_bounds__(256, 2) gemm_out(int H)
{
    __shared__ __align__(16) float shA[4][8 * 136];
    __shared__ __align__(16) float shB[4][16 * 32 * 4];

    int tid = threadIdx.x;
    int row0 = blockIdx.y * 128;
    int col0 = blockIdx.x * 128;
    int b = row0 >> 10;
    int nbase = row0 & (NTOK - 1);
    int cb0 = col0 >> 3;

    int wid = tid >> 5, lane = tid & 31;
    int g = lane >> 2, t = lane & 3;
    int wr = wid >> 2, wc = wid & 3;

    float acc[4][4][4] = {};

    int akk = tid >> 5, aseg = tid & 31;
    const float* aRow = &g_q[((size_t)b * H + akk) * NTOK + nbase + aseg * 4];
    size_t aStride = (size_t)8 * NTOK;

    #define OUT_LOAD(kb, st)                                                     \
    {                                                                            \
        cp16(sAddr(&shA[st][akk * 136 + aseg * 4]), aRow + (size_t)(kb) * aStride); \
        _Pragma("unroll")                                                        \
        for (int i = 0; i < 2; i++) {                                            \
            int c = i * 256 + tid;                                               \
            int cb = c >> 5, ln = c & 31;                                        \
            cp16(sAddr(&shB[st][(cb * 32 + ln) * 4]),                            \
                 &g_WoF[kb][cb0 + cb][ln][0]);                                   \
        }                                                                        \
        CP_COMMIT();                                                             \
    }

    int ksteps = H >> 3;   // 45 or 20 (exact)
    OUT_LOAD(0, 0);
    OUT_LOAD(1, 1);
    OUT_LOAD(2, 2);

    for (int kb = 0; kb < ksteps; kb++) {
        if (kb == ksteps - 1) { CP_WAIT0(); } else { CP_WAIT2(); }
        __syncthreads();
        if (kb + 3 < ksteps) {
            int kn = kb + 3;
            OUT_LOAD(kn, kn & 3);
        }
        int st = kb & 3;
        const float* A = shA[st];
        const float* B = shB[st];

        uint32_t ah[4][4];
        #pragma unroll
        for (int mf = 0; mf < 4; mf++) {
            int rb = wr * 64 + mf * 16;
            ah[mf][0] = __float_as_uint(A[t       * 136 + rb + g]);
            ah[mf][1] = __float_as_uint(A[t       * 136 + rb + g + 8]);
            ah[mf][2] = __float_as_uint(A[(t + 4) * 136 + rb + g]);
            ah[mf][3] = __float_as_uint(A[(t + 4) * 136 + rb + g + 8]);
        }
        #pragma unroll
        for (int nf = 0; nf < 4; nf++) {
            int cb = wc * 4 + nf;
            float4 bf = *(const float4*)&B[(cb * 32 + lane) * 4];
            uint32_t bh[2] = {__float_as_uint(bf.x), __float_as_uint(bf.z)};
            uint32_t bl[2] = {__float_as_uint(bf.y), __float_as_uint(bf.w)};
            #pragma unroll
            for (int mf = 0; mf < 4; mf++) {
                mma_tf32(acc[mf][nf], ah[mf], bh);
                mma_tf32(acc[mf][nf], ah[mf], bl);
            }
        }
    }
    #undef OUT_LOAD

    #pragma unroll
    for (int mf = 0; mf < 4; mf++) {
        #pragma unroll
        for (int nf = 0; nf < 4; nf++) {
            int col = col0 + wc * 32 + nf * 8 + t * 2;
            #pragma unroll
            for (int rr = 0; rr < 2; rr++) {
                int row = row0 + wr * 64 + mf * 16 + g + rr * 8;
                float2* hp = (float2*)&g_h[(size_t)row * DCH + col];
                float2 hv = *hp;
                hv.x += acc[mf][nf][rr * 2];
                hv.y += acc[mf][nf][rr * 2 + 1];
                *hp = hv;
            }
        }
    }
}

// ---------------------------------------------------------------------------
// 1024-pt radix-4 Stockham FFT, 256 threads, ping-pong, result in y.
// ---------------------------------------------------------------------------
template<bool INV>
__device__ __forceinline__ void fft1024(float2* x, float2* y, const float2* tw, int tid)
{
    float2* src = x;
    float2* dst = y;
    #pragma unroll
    for (int s = 0; s < 5; s++) {
        int m = 1 << (2 * s);
        float2 c0 = src[tid];
        float2 c1 = src[tid + 256];
        float2 c2 = src[tid + 512];
        float2 c3 = src[tid + 768];
        float2 t0 = cadd(c0, c2);
        float2 t1 = csub(c0, c2);
        float2 t2 = cadd(c1, c3);
        float2 d  = csub(c1, c3);
        float2 t3 = INV ? make_float2(-d.y, d.x) : make_float2(d.y, -d.x);
        int jm = tid & ~(m - 1);
        float2 w1 = tw[jm];
        if (INV) w1.y = -w1.y;
        float2 w2 = cmul(w1, w1);
        float2 w3 = cmul(w2, w1);
        int base = tid + 3 * jm;
        dst[base]         = cadd(t0, t2);
        dst[base + m]     = cmul(w1, cadd(t1, t3));
        dst[base + 2 * m] = cmul(w2, csub(t0, t2));
        dst[base + 3 * m] = cmul(w3, csub(t1, t3));
        __syncthreads();
        float2* tmp = src; src = dst; dst = tmp;
    }
}

__global__ void fft_filt_kernel(const float* __restrict__ filt, int H)
{
    int h = blockIdx.x;
    int tid = threadIdx.x;
    __shared__ float2 bufA[1024];
    __shared__ float2 bufB[1024];
    __shared__ float2 tw[256];
    {
        float ang = -6.283185307179586f * (float)tid / 1024.f;
        float sn, cs;
        sincosf(ang, &sn, &cs);
        tw[tid] = make_float2(cs, sn);
    }
    for (int n = tid; n < 1024; n += 256)
        bufA[n] = make_float2(filt[(size_t)n * H + h], 0.f);
    __syncthreads();
    fft1024<false>(bufA, bufB, tw, tid);
    for (int f = tid; f < 1024; f += 256)
        g_Ff[h * 1024 + f] = bufB[f];
}

// Packed-pair conv: reads kv directly, gates with q, writes tf32-rounded.
__global__ void conv_kernel(int H)
{
    int h = blockIdx.x;
    int b0 = blockIdx.y * 2, b1 = b0 + 1;
    int tid = threadIdx.x;
    __shared__ float2 bufA[1024];
    __shared__ float2 bufB[1024];
    __shared__ float2 tw[256];
    {
        float ang = -6.283185307179586f * (float)tid / 1024.f;
        float sn, cs;
        sincosf(ang, &sn, &cs);
        tw[tid] = make_float2(cs, sn);
    }

    const float* kv0 = &g_kv[((size_t)b0 * H + h) * NTOK];
    const float* kv1 = &g_kv[((size_t)b1 * H + h) * NTOK];
    float* qp0 = &g_q[((size_t)b0 * H + h) * NTOK];
    float* qp1 = &g_q[((size_t)b1 * H + h) * NTOK];

    {
        float4 u = *(const float4*)&kv0[tid * 4];
        float4 v = *(const float4*)&kv1[tid * 4];
        bufA[tid * 4 + 0] = make_float2(u.x, v.x);
        bufA[tid * 4 + 1] = make_float2(u.y, v.y);
        bufA[tid * 4 + 2] = make_float2(u.z, v.z);
        bufA[tid * 4 + 3] = make_float2(u.w, v.w);
    }
    __syncthreads();
    fft1024<false>(bufA, bufB, tw, tid);

    const float2* Fh = &g_Ff[h * 1024];
    for (int k = tid; k <= 512; k += 256) {
        int nk = (1024 - k) & 1023;
        float2 Z = bufB[k];
        float2 Y = bufB[nk];
        float Ar = 0.5f * (Z.x + Y.x), Ai = 0.5f * (Z.y - Y.y);
        float Br = 0.5f * (Z.y + Y.y), Bi = 0.5f * (Y.x - Z.x);
        float2 F = Fh[k];
        float P1r = Ar * F.x - Ai * F.y, P1i = Ar * F.y + Ai * F.x;
        float P2r = Br * F.x - Bi * F.y, P2i = Br * F.y + Bi * F.x;
        bufA[k] = make_float2(P1r - P2i, P1i + P2r);
        if (k != 0 && k != 512)
            bufA[nk] = make_float2(P1r + P2i, -P1i + P2r);
    }
    __syncthreads();
    fft1024<true>(bufA, bufB, tw, tid);

    const float inv = 1.f / 1024.f;
    {
        float4 q0 = *(const float4*)&qp0[tid * 4];
        float4 q1 = *(const float4*)&qp1[tid * 4];
        float2 c0 = bufB[tid * 4 + 0];
        float2 c1 = bufB[tid * 4 + 1];
        float2 c2 = bufB[tid * 4 + 2];
        float2 c3 = bufB[tid * 4 + 3];
        q0.x = tf32_rna_f(q0.x * c0.x * inv);
        q0.y = tf32_rna_f(q0.y * c1.x * inv);
        q0.z = tf32_rna_f(q0.z * c2.x * inv);
        q0.w = tf32_rna_f(q0.w * c3.x * inv);
        q1.x = tf32_rna_f(q1.x * c0.y * inv);
        q1.y = tf32_rna_f(q1.y * c1.y * inv);
        q1.z = tf32_rna_f(q1.z * c2.y * inv);
        q1.w = tf32_rna_f(q1.w * c3.y * inv);
        *(float4*)&qp0[tid * 4] = q0;
        *(float4*)&qp1[tid * 4] = q1;
    }
}

// ---------------------------------------------------------------------------
// reg_linear + BN partials: 32 tokens per block
// ---------------------------------------------------------------------------
__global__ void __launch_bounds__(256) reglin_kernel(const float* __restrict__ Wm0,
                                                     const float* __restrict__ Wm1)
{
    __shared__ float W0[64 * 64];
    __shared__ float W1[64 * 64];
    __shared__ __align__(16) float hs[8 * 256];
    __shared__ float red0[256], red1[256];
    int tid = threadIdx.x;
    int row0 = blockIdx.x * 32;
    for (int i = tid; i < 4096; i += 256) { W0[i] = Wm0[i]; W1[i] = Wm1[i]; }
    int k = tid & 63, grp = tid >> 6;
    float ls0 = 0.f, ls1 = 0.f;
    for (int batch = 0; batch < 4; batch++) {
        __syncthreads();
        for (int i = tid; i < 2048; i += 256)
            hs[i] = g_h[(size_t)(row0 + batch * 8) * DCH + i];
        __syncthreads();
        #pragma unroll
        for (int tt = 0; tt < 2; tt++) {
            int t = grp * 2 + tt;
            const float* hr = &hs[t * 256];
            float s = 0.f, v0 = 0.f, v1 = 0.f, v2 = 0.f;
            #pragma unroll 8
            for (int m = 0; m < 64; m++) {
                float4 hv = *(const float4*)&hr[m * 4];
                float w0 = W0[m * 64 + k];
                float w1 = W1[m * 64 + k];
                s  += hv.x * w0;
                v0 += hv.y * w1;
                v1 += hv.z * w1;
                v2 += hv.w * w1;
            }
            *(float4*)&g_y[(size_t)(row0 + batch * 8 + t) * DCH + k * 4] = make_float4(s, v0, v1, v2);
            ls0 += s * s;
            ls1 += v0 * v0 + v1 * v1 + v2 * v2;
        }
    }
    red0[tid] = ls0; red1[tid] = ls1;
    __syncthreads();
    if (grp == 0) {
        float t0 = red0[k] + red0[64 + k] + red0[128 + k] + red0[192 + k];
        float t1 = red1[k] + red1[64 + k] + red1[128 + k] + red1[192 + k];
        g_part0[k * NBLK2 + blockIdx.x] = t0;
        g_part1[k * NBLK2 + blockIdx.x] = t1;
    }
}

__global__ void scale_red_kernel(const float* __restrict__ g0, const float* __restrict__ g1)
{
    int c = blockIdx.x;          // 0..127
    int ch = c & 63;
    const float* src = (c < 64) ? &g_part0[(size_t)ch * NBLK2] : &g_part1[(size_t)ch * NBLK2];
    int tid = threadIdx.x;
    float s = 0.f;
    for (int i = tid; i < NBLK2; i += 256) s += src[i];
    __shared__ float red[256];
    red[tid] = s;
    __syncthreads();
    for (int st = 128; st; st >>= 1) {
        if (tid < st) red[tid] += red[tid + st];
        __syncthreads();
    }
    if (tid == 0) {
        float norm = sqrtf(red[0] / (float)RTOT + EPSF);
        if (c < 64) g_scale0[ch] = g0[ch] / norm;
        else        g_scale1[ch] = g1[ch] / norm;
    }
}

__global__ void actres_kernel()
{
    size_t idx = (size_t)blockIdx.x * 256 + threadIdx.x;
    int m = (int)(idx & 63);
    float4 yv = *(float4*)&g_y[idx * 4];
    float s  = yv.x * g_scale0[m];
    float sc = g_scale1[m];
    float v0 = yv.y * sc, v1 = yv.z * sc, v2 = yv.w * sc;
    float sg  = 1.f / (1.f + __expf(-fabsf(s)));
    float vn  = sqrtf(v0 * v0 + v1 * v1 + v2 * v2 + EPSF);
    float sgv = 1.f / (1.f + __expf(-vn));
    float4* hp = (float4*)&g_h[idx * 4];
    float4 hv = *hp;
    hv.x += s * sg;
    hv.y += v0 * sgv;
    hv.z += v1 * sgv;
    hv.w += v2 * sgv;
    *hp = hv;
}

__global__ void pool_kernel(const float* __restrict__ w_out, float* __restrict__ out)
{
    int b = blockIdx.x;
    int tid = threadIdx.x;
    __shared__ float wsh[64];
    if (tid < 64) wsh[tid] = w_out[tid];
    __syncthreads();
    float a0 = 0.f, a1 = 0.f, a2 = 0.f;
    for (int n = tid; n < NTOK; n += 256) {
        const float* hr = &g_h[((size_t)b * NTOK + n) * DCH];
        #pragma unroll 8
        for (int m = 0; m < 64; m++) {
            float w = wsh[m];
            float4 hv = *(const float4*)&hr[m * 4];
            a0 += hv.y * w;
            a1 += hv.z * w;
            a2 += hv.w * w;
        }
    }
    __shared__ float r0[256], r1[256], r2[256];
    r0[tid] = a0; r1[tid] = a1; r2[tid] = a2;
    __syncthreads();
    for (int st = 128; st; st >>= 1) {
        if (tid < st) { r0[tid] += r0[tid + st]; r1[tid] += r1[tid + st]; r2[tid] += r2[tid + st]; }
        __syncthreads();
    }
    if (tid == 0) {
        out[b * 3 + 0] = r0[0] / (float)NTOK;
        out[b * 3 + 1] = r1[0] / (float)NTOK;
        out[b * 3 + 2] = r2[0] / (float)NTOK;
    }
}

// ---------------------------------------------------------------------------
extern "C" void kernel_launch(void* const* d_in, const int* in_sizes, int n_in,
                              void* d_out, int out_size)
{
    (void)in_sizes; (void)n_in; (void)out_size;
    const float* x       = (const float*)d_in[0];
    const float* tok_emb = (const float*)d_in[1];
    const float* Wf      = (const float*)d_in[2];
    const float* wv      = (const float*)d_in[3];
    const float* w_out   = (const float*)d_in[4];
    const int Hs[3] = {360, 360, 160};

    init_h_kernel<<<NTOK, 256>>>(x, tok_emb, Wf, wv);

    for (int L = 0; L < 3; L++) {
        int base = 5 + L * 9;
        const float* Wq   = (const float*)d_in[base + 0];
        const float* Wk   = (const float*)d_in[base + 1];
        const float* Wvw  = (const float*)d_in[base + 2];
        const float* filt = (const float*)d_in[base + 3];
        const float* Wo   = (const float*)d_in[base + 4];
        const float* Wm0  = (const float*)d_in[base + 5];
        const float* Wm1  = (const float*)d_in[base + 6];
        const float* g0   = (const float*)d_in[base + 7];
        const float* g1   = (const float*)d_in[base + 8];
        int H = Hs[L];

        if (H > 256) {
            presplit_cat<384><<<256 * 3 * 384 / 256, 256>>>(Wq, Wk, Wvw, H);
            gemm_in<384><<<dim3(3 * 384 / 128, RTOT / 128), 256>>>(H);
        } else {
            presplit_cat<256><<<256 * 3 * 256 / 256, 256>>>(Wq, Wk, Wvw, H);
            gemm_in<256><<<dim3(3 * 256 / 128, RTOT / 128), 256>>>(H);
        }
        presplit_wo<<<HPADMAX * DCH / 256, 256>>>(Wo, H);
        fft_filt_kernel<<<H, 256>>>(filt, H);
        conv_kernel<<<dim3(H, BSZ / 2), 256>>>(H);
        gemm_out<<<dim3(DCH / 128, RTOT / 128), 256>>>(H);
        reglin_kernel<<<NBLK2, 256>>>(Wm0, Wm1);
        scale_red_kernel<<<128, 256>>>(g0, g1);
        actres_kernel<<<RTOT * 64 / 256, 256>>>();
    }

    pool_kernel<<<BSZ, 256>>>(w_out, (float*)d_out);
}

// round 10
// speedup vs baseline: 1.0849x; 1.0849x over previous
#include <cuda_runtime.h>
#include <math.h>
#include <stdint.h>

// Problem constants
#define BSZ   64
#define NTOK  1024
#define MCH   64
#define DCH   256       // 4*M
#define PDIM  64
#define RTOT  (BSZ*NTOK)   // 65536
#define HMAX  360
#define HPADMAX 384
#define EPSF  1e-5f
#define NBLK2 (RTOT/32)    // 2048 reglin blocks

// -------- scratch (static __device__ globals) --------
__device__ __align__(16) float g_h[(size_t)RTOT*DCH];
__device__ __align__(16) float g_y[(size_t)RTOT*DCH];
__device__ __align__(16) float g_q[(size_t)BSZ*HMAX*NTOK];
__device__ __align__(16) float g_kv[(size_t)BSZ*HMAX*NTOK];
__device__ __align__(16) float2 g_Ff[HMAX*NTOK];
// fragment-packed concatenated weights [Q | KV-interleaved]: (b0h,b0l,b1h,b1l)
__device__ __align__(16) float g_WcF[32][3*HPADMAX/8][32][4];
__device__ __align__(16) float g_WoF[HPADMAX/8][32][32][4];
__device__ float g_part0[MCH*NBLK2];
__device__ float g_part1[MCH*NBLK2];
__device__ float g_scale0[MCH];
__device__ float g_scale1[MCH];

// ---------------------------------------------------------------------------
__device__ __forceinline__ void mma_tf32(float* c, const uint32_t* a, const uint32_t* b)
{
    asm volatile(
        "mma.sync.aligned.m16n8k8.row.col.f32.tf32.tf32.f32 "
        "{%0,%1,%2,%3}, {%4,%5,%6,%7}, {%8,%9}, {%0,%1,%2,%3};\n"
        : "+f"(c[0]), "+f"(c[1]), "+f"(c[2]), "+f"(c[3])
        : "r"(a[0]), "r"(a[1]), "r"(a[2]), "r"(a[3]), "r"(b[0]), "r"(b[1]));
}

__device__ __forceinline__ float tf32_rna_f(float x)
{
    uint32_t r;
    asm("cvt.rna.tf32.f32 %0, %1;" : "=r"(r) : "f"(x));
    return __uint_as_float(r);
}
__device__ __forceinline__ uint32_t rna_bits(float x)
{
    uint32_t r;
    asm("cvt.rna.tf32.f32 %0, %1;" : "=r"(r) : "f"(x));
    return r;
}

__device__ __forceinline__ uint32_t sAddr(const void* p)
{
    return (uint32_t)__cvta_generic_to_shared(p);
}
__device__ __forceinline__ void cp16(uint32_t dst, const void* src)
{
    asm volatile("cp.async.cg.shared.global [%0], [%1], 16;\n" :: "r"(dst), "l"(src));
}
#define CP_COMMIT() asm volatile("cp.async.commit_group;\n")
#define CP_WAIT1()  asm volatile("cp.async.wait_group 1;\n")
#define CP_WAIT0()  asm volatile("cp.async.wait_group 0;\n")

__device__ __forceinline__ float2 cmul(float2 a, float2 b)
{ return make_float2(a.x*b.x - a.y*b.y, a.x*b.y + a.y*b.x); }
__device__ __forceinline__ float2 cadd(float2 a, float2 b){ return make_float2(a.x+b.x, a.y+b.y); }
__device__ __forceinline__ float2 csub(float2 a, float2 b){ return make_float2(a.x-b.x, a.y-b.y); }

// ---------------------------------------------------------------------------
// init h
// ---------------------------------------------------------------------------
__global__ void init_h_kernel(const float* __restrict__ x,
                              const float* __restrict__ tok_emb,
                              const float* __restrict__ Wf,
                              const float* __restrict__ wv)
{
    int n = blockIdx.x;
    int tid = threadIdx.x;   // 256
    __shared__ float f[PDIM];
    __shared__ float s0[MCH];
    if (tid < PDIM) {
        int p = tid;
        int j2 = p & ~1;
        float div = expf(-logf(10000.0f) * (float)j2 / (float)PDIM);
        float ang = (float)n * div;
        float pe = (p & 1) ? cosf(ang) : sinf(ang);
        int tt = (n == NTOK - 1) ? 2 : (n & 1);
        f[p] = pe + tok_emb[tt * PDIM + p];
    }
    __syncthreads();
    if (tid < MCH) {
        float acc = 0.f;
        #pragma unroll 8
        for (int p = 0; p < PDIM; p++) acc += f[p] * Wf[p * MCH + tid];
        s0[tid] = acc;
    }
    __syncthreads();
    int m = tid >> 2, r = tid & 3;
    float wvm = wv[m];
    float sv = s0[m];
    for (int b = 0; b < BSZ; b++) {
        float val;
        if (r == 0) val = sv;
        else        val = x[((size_t)b * NTOK + n) * 3 + (r - 1)] * wvm;
        g_h[((size_t)b * NTOK + n) * DCH + tid] = val;
    }
}

// ---------------------------------------------------------------------------
// weight pre-split. Column map over 3*HP:
//   c < HP          -> Wq column c
//   c >= HP         -> j=c-HP; h=j>>1; even j -> Wk[h], odd j -> Wv[h]
// ---------------------------------------------------------------------------
template<int HP>
__global__ void presplit_cat(const float* __restrict__ Wq,
                             const float* __restrict__ Wk,
                             const float* __restrict__ Wv2, int H)
{
    int idx = blockIdx.x * 256 + threadIdx.x;   // over 256 * 3*HP
    int k = idx / (3 * HP), c = idx % (3 * HP);
    const float* W;
    int h;
    if (c < HP) { W = Wq; h = c; }
    else {
        int j = c - HP;
        h = j >> 1;
        W = (j & 1) ? Wv2 : Wk;
    }
    int kb = k >> 3, kk = k & 7;
    int t = kk & 3, pos = kk >> 2;
    int cb = c >> 3, lane = (c & 7) * 4 + t;
    float w = (h < H) ? W[(size_t)k * H + h] : 0.f;
    float hi = tf32_rna_f(w);
    g_WcF[kb][cb][lane][pos * 2]     = hi;
    g_WcF[kb][cb][lane][pos * 2 + 1] = w - hi;
}

__global__ void presplit_wo(const float* __restrict__ Wo, int H)
{
    int idx = blockIdx.x * 256 + threadIdx.x;   // over HPADMAX*256
    int k = idx >> 8, n = idx & 255;
    int kb = k >> 3, kk = k & 7;
    int t = kk & 3, pos = kk >> 2;
    int cb = n >> 3, lane = (n & 7) * 4 + t;
    float w = (k < H) ? Wo[(size_t)k * DCH + n] : 0.f;
    float hi = tf32_rna_f(w);
    g_WoF[kb][cb][lane][pos * 2]     = hi;
    g_WoF[kb][cb][lane][pos * 2 + 1] = w - hi;
}

// ---------------------------------------------------------------------------
// Merged qkv GEMM: C[R, 3*HP] = A[R,256] @ Wcat. Tile 128x128, kstep 16
// (two k8 sub-blocks per step), 3-stage cp.async ring, distance 2, loads
// issued after the MMA block (proven R8 ordering). 16 barriers total.
// ---------------------------------------------------------------------------
template<int HP>
__global__ void __launch_bounds__(256, 2) gemm_in(int H)
{
    __shared__ __align__(16) float shA[3][128 * 20];        // [row][k16 pad 20]
    __shared__ __align__(16) float shB[3][2 * 16 * 32 * 4]; // two k8 blocks

    int tid = threadIdx.x;
    int row0 = blockIdx.y * 128;
    int col0 = blockIdx.x * 128;        // over 3*HP
    int b = row0 >> 10;
    int nbase = row0 & (NTOK - 1);
    int cb0 = col0 >> 3;

    int wid = tid >> 5, lane = tid & 31;
    int g = lane >> 2, t = lane & 3;
    int wr = wid >> 2, wc = wid & 3;

    float acc[4][4][4] = {};

    int ar2 = tid >> 2, akq = tid & 3;

    #define IN_LOAD(kb, st)                                                   \
    {                                                                         \
        _Pragma("unroll")                                                     \
        for (int i = 0; i < 2; i++) {                                         \
            int row = ar2 + i * 64;                                           \
            cp16(sAddr(&shA[st][row * 20 + akq * 4]),                         \
                 &g_h[(size_t)(row0 + row) * DCH + (kb) * 16 + akq * 4]);     \
        }                                                                     \
        _Pragma("unroll")                                                     \
        for (int i = 0; i < 4; i++) {                                         \
            int c = i * 256 + tid;                                            \
            int kbb = c >> 9, rem = c & 511;                                  \
            int cb = rem >> 5, ln = rem & 31;                                 \
            cp16(sAddr(&shB[st][kbb * 2048 + (cb * 32 + ln) * 4]),            \
                 &g_WcF[(kb) * 2 + kbb][cb0 + cb][ln][0]);                    \
        }                                                                     \
        CP_COMMIT();                                                          \
    }

    IN_LOAD(0, 0);
    IN_LOAD(1, 1);

    for (int kb = 0; kb < 16; kb++) {
        if (kb == 15) { CP_WAIT0(); } else { CP_WAIT1(); }
        __syncthreads();
        int st = kb % 3;
        const float* A = shA[st];
        const float* B = shB[st];

        #pragma unroll
        for (int kbb = 0; kbb < 2; kbb++) {
            int kk = kbb * 8;
            uint32_t ah[4][4];
            #pragma unroll
            for (int mf = 0; mf < 4; mf++) {
                int rb = wr * 64 + mf * 16;
                ah[mf][0] = rna_bits(A[(rb + g)     * 20 + kk + t]);
                ah[mf][1] = rna_bits(A[(rb + g + 8) * 20 + kk + t]);
                ah[mf][2] = rna_bits(A[(rb + g)     * 20 + kk + t + 4]);
                ah[mf][3] = rna_bits(A[(rb + g + 8) * 20 + kk + t + 4]);
            }
            #pragma unroll
            for (int nf = 0; nf < 4; nf++) {
                int cb = wc * 4 + nf;
                float4 bf = *(const float4*)&B[kbb * 2048 + (cb * 32 + lane) * 4];
                uint32_t bh[2] = {__float_as_uint(bf.x), __float_as_uint(bf.z)};
                uint32_t bl[2] = {__float_as_uint(bf.y), __float_as_uint(bf.w)};
                #pragma unroll
                for (int mf = 0; mf < 4; mf++) {
                    mma_tf32(acc[mf][nf], ah[mf], bh);
                    mma_tf32(acc[mf][nf], ah[mf], bl);
                }
            }
        }
        if (kb + 2 < 16) {
            int kn = kb + 2;
            IN_LOAD(kn, kn % 3);
        }
    }
    #undef IN_LOAD

    if (col0 < HP) {
        // Q region (tiles never straddle: HP % 128 == 0)
        #pragma unroll
        for (int mf = 0; mf < 4; mf++) {
            #pragma unroll
            for (int nf = 0; nf < 4; nf++) {
                #pragma unroll
                for (int cc = 0; cc < 2; cc++) {
                    int col = col0 + wc * 32 + nf * 8 + t * 2 + cc;
                    if (col < H) {
                        size_t base = ((size_t)b * H + col) * NTOK + nbase + wr * 64 + mf * 16 + g;
                        g_q[base]     = acc[mf][nf][cc];
                        g_q[base + 8] = acc[mf][nf][cc + 2];
                    }
                }
            }
        }
    } else {
        // KV region: thread's two adjacent cols are (k_h, v_h) of same h
        #pragma unroll
        for (int mf = 0; mf < 4; mf++) {
            #pragma unroll
            for (int nf = 0; nf < 4; nf++) {
                int h = ((col0 - HP) >> 1) + wc * 16 + nf * 4 + t;
                if (h < H) {
                    size_t base = ((size_t)b * H + h) * NTOK + nbase + wr * 64 + mf * 16 + g;
                    g_kv[base]     = acc[mf][nf][0] * acc[mf][nf][1];
                    g_kv[base + 8] = acc[mf][nf][2] * acc[mf][nf][3];
                }
            }
        }
    }
}

// ---------------------------------------------------------------------------
// Wo GEMM + residual: g_h[R,256] += G[R,H] @ Wo[H,256].
// Tile 128x128, kstep 16, 3-stage ring, loads after MMAs. A rows past H are
// clamped (they multiply zero-padded WoF columns -> contribute 0).
// ---------------------------------------------------------------------------
__global__ void __launch_bounds__(256, 2) gemm_out(int H)
{
    __shared__ __align__(16) float shA[3][16 * 136];
    __shared__ __align__(16) float shB[3][2 * 16 * 32 * 4];

    int tid = threadIdx.x;
    int row0 = blockIdx.y * 128;
    int col0 = blockIdx.x * 128;
    int b = row0 >> 10;
    int nbase = row0 & (NTOK - 1);
    int cb0 = col0 >> 3;

    int wid = tid >> 5, lane = tid & 31;
    int g = lane >> 2, t = lane & 3;
    int wr = wid >> 2, wc = wid & 3;

    float acc[4][4][4] = {};

    int akk = tid >> 5, aseg = tid & 31;   // akk 0..7, two i-iters cover k 0..15

    #define OUT_LOAD(kb, st)                                                     \
    {                                                                            \
        _Pragma("unroll")                                                        \
        for (int i = 0; i < 2; i++) {                                            \
            int k = akk + i * 8;                                                 \
            int krow = (kb) * 16 + k;                                            \
            if (krow > H - 1) krow = H - 1;                                      \
            cp16(sAddr(&shA[st][k * 136 + aseg * 4]),                            \
                 &g_q[((size_t)b * H + krow) * NTOK + nbase + aseg * 4]);        \
        }                                                                        \
        _Pragma("unroll")                                                        \
        for (int i = 0; i < 4; i++) {                                            \
            int c = i * 256 + tid;                                               \
            int kbb = c >> 9, rem = c & 511;                                     \
            int cb = rem >> 5, ln = rem & 31;                                    \
            cp16(sAddr(&shB[st][kbb * 2048 + (cb * 32 + ln) * 4]),               \
                 &g_WoF[(kb) * 2 + kbb][cb0 + cb][ln][0]);                       \
        }                                                                        \
        CP_COMMIT();                                                             \
    }

    int ksteps = (H + 15) >> 4;   // 23 or 10
    OUT_LOAD(0, 0);
    OUT_LOAD(1, 1);

    for (int kb = 0; kb < ksteps; kb++) {
        if (kb == ksteps - 1) { CP_WAIT0(); } else { CP_WAIT1(); }
        __syncthreads();
        int st = kb % 3;
        const float* A = shA[st];
        const float* B = shB[st];

        #pragma unroll
        for (int kbb = 0; kbb < 2; kbb++) {
            int kk = kbb * 8;
            uint32_t ah[4][4];
            #pragma unroll
            for (int mf = 0; mf < 4; mf++) {
                int rb = wr * 64 + mf * 16;
                ah[mf][0] = __float_as_uint(A[(kk + t)     * 136 + rb + g]);
                ah[mf][1] = __float_as_uint(A[(kk + t)     * 136 + rb + g + 8]);
                ah[mf][2] = __float_as_uint(A[(kk + t + 4) * 136 + rb + g]);
                ah[mf][3] = __float_as_uint(A[(kk + t + 4) * 136 + rb + g + 8]);
            }
            #pragma unroll
            for (int nf = 0; nf < 4; nf++) {
                int cb = wc * 4 + nf;
                float4 bf = *(const float4*)&B[kbb * 2048 + (cb * 32 + lane) * 4];
                uint32_t bh[2] = {__float_as_uint(bf.x), __float_as_uint(bf.z)};
                uint32_t bl[2] = {__float_as_uint(bf.y), __float_as_uint(bf.w)};
                #pragma unroll
                for (int mf = 0; mf < 4; mf++) {
                    mma_tf32(acc[mf][nf], ah[mf], bh);
                    mma_tf32(acc[mf][nf], ah[mf], bl);
                }
            }
        }
        if (kb + 2 < ksteps) {
            int kn = kb + 2;
            OUT_LOAD(kn, kn % 3);
        }
    }
    #undef OUT_LOAD

    #pragma unroll
    for (int mf = 0; mf < 4; mf++) {
        #pragma unroll
        for (int nf = 0; nf < 4; nf++) {
            int col = col0 + wc * 32 + nf * 8 + t * 2;
            #pragma unroll
            for (int rr = 0; rr < 2; rr++) {
                int row = row0 + wr * 64 + mf * 16 + g + rr * 8;
                float2* hp = (float2*)&g_h[(size_t)row * DCH + col];
                float2 hv = *hp;
                hv.x += acc[mf][nf][rr * 2];
                hv.y += acc[mf][nf][rr * 2 + 1];
                *hp = hv;
            }
        }
    }
}

// ---------------------------------------------------------------------------
// 1024-pt radix-4 Stockham FFT, 256 threads, ping-pong, result in y.
// ---------------------------------------------------------------------------
template<bool INV>
__device__ __forceinline__ void fft1024(float2* x, float2* y, const float2* tw, int tid)
{
    float2* src = x;
    float2* dst = y;
    #pragma unroll
    for (int s = 0; s < 5; s++) {
        int m = 1 << (2 * s);
        float2 c0 = src[tid];
        float2 c1 = src[tid + 256];
        float2 c2 = src[tid + 512];
        float2 c3 = src[tid + 768];
        float2 t0 = cadd(c0, c2);
        float2 t1 = csub(c0, c2);
        float2 t2 = cadd(c1, c3);
        float2 d  = csub(c1, c3);
        float2 t3 = INV ? make_float2(-d.y, d.x) : make_float2(d.y, -d.x);
        int jm = tid & ~(m - 1);
        float2 w1 = tw[jm];
        if (INV) w1.y = -w1.y;
        float2 w2 = cmul(w1, w1);
        float2 w3 = cmul(w2, w1);
        int base = tid + 3 * jm;
        dst[base]         = cadd(t0, t2);
        dst[base + m]     = cmul(w1, cadd(t1, t3));
        dst[base + 2 * m] = cmul(w2, csub(t0, t2));
        dst[base + 3 * m] = cmul(w3, csub(t1, t3));
        __syncthreads();
        float2* tmp = src; src = dst; dst = tmp;
    }
}

__global__ void fft_filt_kernel(const float* __restrict__ filt, int H)
{
    int h = blockIdx.x;
    int tid = threadIdx.x;
    __shared__ float2 bufA[1024];
    __shared__ float2 bufB[1024];
    __shared__ float2 tw[256];
    {
        float ang = -6.283185307179586f * (float)tid / 1024.f;
        float sn, cs;
        sincosf(ang, &sn, &cs);
        tw[tid] = make_float2(cs, sn);
    }
    for (int n = tid; n < 1024; n += 256)
        bufA[n] = make_float2(filt[(size_t)n * H + h], 0.f);
    __syncthreads();
    fft1024<false>(bufA, bufB, tw, tid);
    for (int f = tid; f < 1024; f += 256)
        g_Ff[h * 1024 + f] = bufB[f];
}

// Packed-pair conv: reads kv directly, gates with q, writes tf32-rounded.
__global__ void conv_kernel(int H)
{
    int h = blockIdx.x;
    int b0 = blockIdx.y * 2, b1 = b0 + 1;
    int tid = threadIdx.x;
    __shared__ float2 bufA[1024];
    __shared__ float2 bufB[1024];
    __shared__ float2 tw[256];
    {
        float ang = -6.283185307179586f * (float)tid / 1024.f;
        float sn, cs;
        sincosf(ang, &sn, &cs);
        tw[tid] = make_float2(cs, sn);
    }

    const float* kv0 = &g_kv[((size_t)b0 * H + h) * NTOK];
    const float* kv1 = &g_kv[((size_t)b1 * H + h) * NTOK];
    float* qp0 = &g_q[((size_t)b0 * H + h) * NTOK];
    float* qp1 = &g_q[((size_t)b1 * H + h) * NTOK];

    {
        float4 u = *(const float4*)&kv0[tid * 4];
        float4 v = *(const float4*)&kv1[tid * 4];
        bufA[tid * 4 + 0] = make_float2(u.x, v.x);
        bufA[tid * 4 + 1] = make_float2(u.y, v.y);
        bufA[tid * 4 + 2] = make_float2(u.z, v.z);
        bufA[tid * 4 + 3] = make_float2(u.w, v.w);
    }
    __syncthreads();
    fft1024<false>(bufA, bufB, tw, tid);

    const float2* Fh = &g_Ff[h * 1024];
    for (int k = tid; k <= 512; k += 256) {
        int nk = (1024 - k) & 1023;
        float2 Z = bufB[k];
        float2 Y = bufB[nk];
        float Ar = 0.5f * (Z.x + Y.x), Ai = 0.5f * (Z.y - Y.y);
        float Br = 0.5f * (Z.y + Y.y), Bi = 0.5f * (Y.x - Z.x);
        float2 F = Fh[k];
        float P1r = Ar * F.x - Ai * F.y, P1i = Ar * F.y + Ai * F.x;
        float P2r = Br * F.x - Bi * F.y, P2i = Br * F.y + Bi * F.x;
        bufA[k] = make_float2(P1r - P2i, P1i + P2r);
        if (k != 0 && k != 512)
            bufA[nk] = make_float2(P1r + P2i, -P1i + P2r);
    }
    __syncthreads();
    fft1024<true>(bufA, bufB, tw, tid);

    const float inv = 1.f / 1024.f;
    {
        float4 q0 = *(const float4*)&qp0[tid * 4];
        float4 q1 = *(const float4*)&qp1[tid * 4];
        float2 c0 = bufB[tid * 4 + 0];
        float2 c1 = bufB[tid * 4 + 1];
        float2 c2 = bufB[tid * 4 + 2];
        float2 c3 = bufB[tid * 4 + 3];
        q0.x = tf32_rna_f(q0.x * c0.x * inv);
        q0.y = tf32_rna_f(q0.y * c1.x * inv);
        q0.z = tf32_rna_f(q0.z * c2.x * inv);
        q0.w = tf32_rna_f(q0.w * c3.x * inv);
        q1.x = tf32_rna_f(q1.x * c0.y * inv);
        q1.y = tf32_rna_f(q1.y * c1.y * inv);
        q1.z = tf32_rna_f(q1.z * c2.y * inv);
        q1.w = tf32_rna_f(q1.w * c3.y * inv);
        *(float4*)&qp0[tid * 4] = q0;
        *(float4*)&qp1[tid * 4] = q1;
    }
}

// ---------------------------------------------------------------------------
// reg_linear + BN partials: 32 tokens per block
// ---------------------------------------------------------------------------
__global__ void __launch_bounds__(256) reglin_kernel(const float* __restrict__ Wm0,
                                                     const float* __restrict__ Wm1)
{
    __shared__ float W0[64 * 64];
    __shared__ float W1[64 * 64];
    __shared__ __align__(16) float hs[8 * 256];
    __shared__ float red0[256], red1[256];
    int tid = threadIdx.x;
    int row0 = blockIdx.x * 32;
    for (int i = tid; i < 4096; i += 256) { W0[i] = Wm0[i]; W1[i] = Wm1[i]; }
    int k = tid & 63, grp = tid >> 6;
    float ls0 = 0.f, ls1 = 0.f;
    for (int batch = 0; batch < 4; batch++) {
        __syncthreads();
        for (int i = tid; i < 2048; i += 256)
            hs[i] = g_h[(size_t)(row0 + batch * 8) * DCH + i];
        __syncthreads();
        #pragma unroll
        for (int tt = 0; tt < 2; tt++) {
            int t = grp * 2 + tt;
            const float* hr = &hs[t * 256];
            float s = 0.f, v0 = 0.f, v1 = 0.f, v2 = 0.f;
            #pragma unroll 8
            for (int m = 0; m < 64; m++) {
                float4 hv = *(const float4*)&hr[m * 4];
                float w0 = W0[m * 64 + k];
                float w1 = W1[m * 64 + k];
                s  += hv.x * w0;
                v0 += hv.y * w1;
                v1 += hv.z * w1;
                v2 += hv.w * w1;
            }
            *(float4*)&g_y[(size_t)(row0 + batch * 8 + t) * DCH + k * 4] = make_float4(s, v0, v1, v2);
            ls0 += s * s;
            ls1 += v0 * v0 + v1 * v1 + v2 * v2;
        }
    }
    red0[tid] = ls0; red1[tid] = ls1;
    __syncthreads();
    if (grp == 0) {
        float t0 = red0[k] + red0[64 + k] + red0[128 + k] + red0[192 + k];
        float t1 = red1[k] + red1[64 + k] + red1[128 + k] + red1[192 + k];
        g_part0[k * NBLK2 + blockIdx.x] = t0;
        g_part1[k * NBLK2 + blockIdx.x] = t1;
    }
}

__global__ void scale_red_kernel(const float* __restrict__ g0, const float* __restrict__ g1)
{
    int c = blockIdx.x;          // 0..127
    int ch = c & 63;
    const float* src = (c < 64) ? &g_part0[(size_t)ch * NBLK2] : &g_part1[(size_t)ch * NBLK2];
    int tid = threadIdx.x;
    float s = 0.f;
    for (int i = tid; i < NBLK2; i += 256) s += src[i];
    __shared__ float red[256];
    red[tid] = s;
    __syncthreads();
    for (int st = 128; st; st >>= 1) {
        if (tid < st) red[tid] += red[tid + st];
        __syncthreads();
    }
    if (tid == 0) {
        float norm = sqrtf(red[0] / (float)RTOT + EPSF);
        if (c < 64) g_scale0[ch] = g0[ch] / norm;
        else        g_scale1[ch] = g1[ch] / norm;
    }
}

__global__ void actres_kernel()
{
    size_t idx = (size_t)blockIdx.x * 256 + threadIdx.x;
    int m = (int)(idx & 63);
    float4 yv = *(float4*)&g_y[idx * 4];
    float s  = yv.x * g_scale0[m];
    float sc = g_scale1[m];
    float v0 = yv.y * sc, v1 = yv.z * sc, v2 = yv.w * sc;
    float sg  = 1.f / (1.f + __expf(-fabsf(s)));
    float vn  = sqrtf(v0 * v0 + v1 * v1 + v2 * v2 + EPSF);
    float sgv = 1.f / (1.f + __expf(-vn));
    float4* hp = (float4*)&g_h[idx * 4];
    float4 hv = *hp;
    hv.x += s * sg;
    hv.y += v0 * sgv;
    hv.z += v1 * sgv;
    hv.w += v2 * sgv;
    *hp = hv;
}

__global__ void pool_kernel(const float* __restrict__ w_out, float* __restrict__ out)
{
    int b = blockIdx.x;
    int tid = threadIdx.x;
    __shared__ float wsh[64];
    if (tid < 64) wsh[tid] = w_out[tid];
    __syncthreads();
    float a0 = 0.f, a1 = 0.f, a2 = 0.f;
    for (int n = tid; n < NTOK; n += 256) {
        const float* hr = &g_h[((size_t)b * NTOK + n) * DCH];
        #pragma unroll 8
        for (int m = 0; m < 64; m++) {
            float w = wsh[m];
            float4 hv = *(const float4*)&hr[m * 4];
            a0 += hv.y * w;
            a1 += hv.z * w;
            a2 += hv.w * w;
        }
    }
    __shared__ float r0[256], r1[256], r2[256];
    r0[tid] = a0; r1[tid] = a1; r2[tid] = a2;
    __syncthreads();
    for (int st = 128; st; st >>= 1) {
        if (tid < st) { r0[tid] += r0[tid + st]; r1[tid] += r1[tid + st]; r2[tid] += r2[tid + st]; }
        __syncthreads();
    }
    if (tid == 0) {
        out[b * 3 + 0] = r0[0] / (float)NTOK;
        out[b * 3 + 1] = r1[0] / (float)NTOK;
        out[b * 3 + 2] = r2[0] / (float)NTOK;
    }
}

// ---------------------------------------------------------------------------
extern "C" void kernel_launch(void* const* d_in, const int* in_sizes, int n_in,
                              void* d_out, int out_size)
{
    (void)in_sizes; (void)n_in; (void)out_size;
    const float* x       = (const float*)d_in[0];
    const float* tok_emb = (const float*)d_in[1];
    const float* Wf      = (const float*)d_in[2];
    const float* wv      = (const float*)d_in[3];
    const float* w_out   = (const float*)d_in[4];
    const int Hs[3] = {360, 360, 160};

    init_h_kernel<<<NTOK, 256>>>(x, tok_emb, Wf, wv);

    for (int L = 0; L < 3; L++) {
        int base = 5 + L * 9;
        const float* Wq   = (const float*)d_in[base + 0];
        const float* Wk   = (const float*)d_in[base + 1];
        const float* Wvw  = (const float*)d_in[base + 2];
        const float* filt = (const float*)d_in[base + 3];
        const float* Wo   = (const float*)d_in[base + 4];
        const float* Wm0  = (const float*)d_in[base + 5];
        const float* Wm1  = (const float*)d_in[base + 6];
        const float* g0   = (const float*)d_in[base + 7];
        const float* g1   = (const float*)d_in[base + 8];
        int H = Hs[L];

        if (H > 256) {
            presplit_cat<384><<<256 * 3 * 384 / 256, 256>>>(Wq, Wk, Wvw, H);
            gemm_in<384><<<dim3(3 * 384 / 128, RTOT / 128), 256>>>(H);
        } else {
            presplit_cat<256><<<256 * 3 * 256 / 256, 256>>>(Wq, Wk, Wvw, H);
            gemm_in<256><<<dim3(3 * 256 / 128, RTOT / 128), 256>>>(H);
        }
        presplit_wo<<<HPADMAX * DCH / 256, 256>>>(Wo, H);
        fft_filt_kernel<<<H, 256>>>(filt, H);
        conv_kernel<<<dim3(H, BSZ / 2), 256>>>(H);
        gemm_out<<<dim3(DCH / 128, RTOT / 128), 256>>>(H);
        reglin_kernel<<<NBLK2, 256>>>(Wm0, Wm1);
        scale_red_kernel<<<128, 256>>>(g0, g1);
        actres_kernel<<<RTOT * 64 / 256, 256>>>();
    }

    pool_kernel<<<BSZ, 256>>>(w_out, (float*)d_out);
}

// round 11
// speedup vs baseline: 1.3779x; 1.2700x over previous
#include <cuda_runtime.h>
#include <math.h>
#include <stdint.h>

// Problem constants
#define BSZ   64
#define NTOK  1024
#define MCH   64
#define DCH   256       // 4*M
#define PDIM  64
#define RTOT  (BSZ*NTOK)   // 65536
#define HMAX  360
#define HPADMAX 384
#define EPSF  1e-5f
#define NBLK2 (RTOT/32)    // 2048 reglin blocks

// -------- scratch (static __device__ globals) --------
__device__ __align__(16) float g_h[(size_t)RTOT*DCH];
__device__ __align__(16) float g_y[(size_t)RTOT*DCH];
__device__ __align__(16) float g_q[(size_t)BSZ*HMAX*NTOK];
__device__ __align__(16) float g_kv[(size_t)BSZ*HMAX*NTOK];
__device__ __align__(16) float2 g_Ff[HMAX*NTOK];
// fragment-packed weights, 1-term tf32, k16 granularity:
// [kb16][cb][lane][4 words: g0w0, g0w1, g1w0, g1w1]
__device__ __align__(16) float g_WcF[16][3*HPADMAX/8][32][4];
__device__ __align__(16) float g_WoF[HPADMAX/16][32][32][4];
__device__ float g_part0[MCH*NBLK2];
__device__ float g_part1[MCH*NBLK2];
__device__ float g_scale0[MCH];
__device__ float g_scale1[MCH];

// ---------------------------------------------------------------------------
__device__ __forceinline__ void mma_tf32(float* c, const uint32_t* a, const uint32_t* b)
{
    asm volatile(
        "mma.sync.aligned.m16n8k8.row.col.f32.tf32.tf32.f32 "
        "{%0,%1,%2,%3}, {%4,%5,%6,%7}, {%8,%9}, {%0,%1,%2,%3};\n"
        : "+f"(c[0]), "+f"(c[1]), "+f"(c[2]), "+f"(c[3])
        : "r"(a[0]), "r"(a[1]), "r"(a[2]), "r"(a[3]), "r"(b[0]), "r"(b[1]));
}

__device__ __forceinline__ float tf32_rna_f(float x)
{
    uint32_t r;
    asm("cvt.rna.tf32.f32 %0, %1;" : "=r"(r) : "f"(x));
    return __uint_as_float(r);
}
__device__ __forceinline__ uint32_t rna_bits(float x)
{
    uint32_t r;
    asm("cvt.rna.tf32.f32 %0, %1;" : "=r"(r) : "f"(x));
    return r;
}

__device__ __forceinline__ uint32_t sAddr(const void* p)
{
    return (uint32_t)__cvta_generic_to_shared(p);
}
__device__ __forceinline__ void cp16(uint32_t dst, const void* src)
{
    asm volatile("cp.async.cg.shared.global [%0], [%1], 16;\n" :: "r"(dst), "l"(src));
}
#define CP_COMMIT() asm volatile("cp.async.commit_group;\n")
#define CP_WAIT1()  asm volatile("cp.async.wait_group 1;\n")
#define CP_WAIT0()  asm volatile("cp.async.wait_group 0;\n")

__device__ __forceinline__ float2 cmul(float2 a, float2 b)
{ return make_float2(a.x*b.x - a.y*b.y, a.x*b.y + a.y*b.x); }
__device__ __forceinline__ float2 cadd(float2 a, float2 b){ return make_float2(a.x+b.x, a.y+b.y); }
__device__ __forceinline__ float2 csub(float2 a, float2 b){ return make_float2(a.x-b.x, a.y-b.y); }

// ---------------------------------------------------------------------------
// init h
// ---------------------------------------------------------------------------
__global__ void init_h_kernel(const float* __restrict__ x,
                              const float* __restrict__ tok_emb,
                              const float* __restrict__ Wf,
                              const float* __restrict__ wv)
{
    int n = blockIdx.x;
    int tid = threadIdx.x;   // 256
    __shared__ float f[PDIM];
    __shared__ float s0[MCH];
    if (tid < PDIM) {
        int p = tid;
        int j2 = p & ~1;
        float div = expf(-logf(10000.0f) * (float)j2 / (float)PDIM);
        float ang = (float)n * div;
        float pe = (p & 1) ? cosf(ang) : sinf(ang);
        int tt = (n == NTOK - 1) ? 2 : (n & 1);
        f[p] = pe + tok_emb[tt * PDIM + p];
    }
    __syncthreads();
    if (tid < MCH) {
        float acc = 0.f;
        #pragma unroll 8
        for (int p = 0; p < PDIM; p++) acc += f[p] * Wf[p * MCH + tid];
        s0[tid] = acc;
    }
    __syncthreads();
    int m = tid >> 2, r = tid & 3;
    float wvm = wv[m];
    float sv = s0[m];
    for (int b = 0; b < BSZ; b++) {
        float val;
        if (r == 0) val = sv;
        else        val = x[((size_t)b * NTOK + n) * 3 + (r - 1)] * wvm;
        g_h[((size_t)b * NTOK + n) * DCH + tid] = val;
    }
}

// ---------------------------------------------------------------------------
// weight pre-split (1-term RNA tf32). Column map over 3*HP:
//   c < HP  -> Wq column c
//   c >= HP -> j=c-HP; h=j>>1; even j -> Wk[h], odd j -> Wv[h]
// Word layout per (kb16, cb, lane): grp = (k&15)>>3, pos = (k&7)>>2,
// word = grp*2+pos; t = k&3; lane = (c&7)*4 + t.
// ---------------------------------------------------------------------------
template<int HP>
__global__ void presplit_cat(const float* __restrict__ Wq,
                             const float* __restrict__ Wk,
                             const float* __restrict__ Wv2, int H)
{
    int idx = blockIdx.x * 256 + threadIdx.x;   // over 256 * 3*HP
    int k = idx / (3 * HP), c = idx % (3 * HP);
    const float* W;
    int h;
    if (c < HP) { W = Wq; h = c; }
    else {
        int j = c - HP;
        h = j >> 1;
        W = (j & 1) ? Wv2 : Wk;
    }
    int kb = k >> 4, kk = k & 15;
    int grp = kk >> 3, kk8 = kk & 7;
    int t = kk8 & 3, pos = kk8 >> 2;
    int cb = c >> 3, lane = (c & 7) * 4 + t;
    float w = (h < H) ? W[(size_t)k * H + h] : 0.f;
    g_WcF[kb][cb][lane][grp * 2 + pos] = tf32_rna_f(w);
}

__global__ void presplit_wo(const float* __restrict__ Wo, int H)
{
    int idx = blockIdx.x * 256 + threadIdx.x;   // over HPADMAX*256
    int k = idx >> 8, n = idx & 255;
    int kb = k >> 4, kk = k & 15;
    int grp = kk >> 3, kk8 = kk & 7;
    int t = kk8 & 3, pos = kk8 >> 2;
    int cb = n >> 3, lane = (n & 7) * 4 + t;
    float w = (k < H) ? Wo[(size_t)k * DCH + n] : 0.f;
    g_WoF[kb][cb][lane][grp * 2 + pos] = tf32_rna_f(w);
}

// ---------------------------------------------------------------------------
// Merged qkv GEMM: C[R, 3*HP] = A[R,256] @ Wcat. Tile 128x128, kstep 16,
// 1-term tf32 B, 3-stage cp.async ring distance 2, loads after MMAs.
// Q-region tiles write q; KV-region tiles write k*v directly.
// ---------------------------------------------------------------------------
template<int HP>
__global__ void __launch_bounds__(256, 2) gemm_in(int H)
{
    __shared__ __align__(16) float shA[3][128 * 20];        // [row][k16 pad 20]
    __shared__ __align__(16) float shB[3][16 * 32 * 4];     // one float4 per (cb,lane)

    int tid = threadIdx.x;
    int row0 = blockIdx.y * 128;
    int col0 = blockIdx.x * 128;        // over 3*HP
    int b = row0 >> 10;
    int nbase = row0 & (NTOK - 1);
    int cb0 = col0 >> 3;

    int wid = tid >> 5, lane = tid & 31;
    int g = lane >> 2, t = lane & 3;
    int wr = wid >> 2, wc = wid & 3;

    float acc[4][4][4] = {};

    int ar2 = tid >> 2, akq = tid & 3;

    #define IN_LOAD(kb, st)                                                   \
    {                                                                         \
        _Pragma("unroll")                                                     \
        for (int i = 0; i < 2; i++) {                                         \
            int row = ar2 + i * 64;                                           \
            cp16(sAddr(&shA[st][row * 20 + akq * 4]),                         \
                 &g_h[(size_t)(row0 + row) * DCH + (kb) * 16 + akq * 4]);     \
        }                                                                     \
        _Pragma("unroll")                                                     \
        for (int i = 0; i < 2; i++) {                                         \
            int c = i * 256 + tid;                                            \
            int cb = c >> 5, ln = c & 31;                                     \
            cp16(sAddr(&shB[st][(cb * 32 + ln) * 4]),                         \
                 &g_WcF[kb][cb0 + cb][ln][0]);                                \
        }                                                                     \
        CP_COMMIT();                                                          \
    }

    IN_LOAD(0, 0);
    IN_LOAD(1, 1);

    for (int kb = 0; kb < 16; kb++) {
        if (kb == 15) { CP_WAIT0(); } else { CP_WAIT1(); }
        __syncthreads();
        int st = kb % 3;
        const float* A = shA[st];
        const float* B = shB[st];

        // A fragments for both k8 groups
        uint32_t ah[2][4][4];
        #pragma unroll
        for (int grp = 0; grp < 2; grp++) {
            int kk = grp * 8;
            #pragma unroll
            for (int mf = 0; mf < 4; mf++) {
                int rb = wr * 64 + mf * 16;
                ah[grp][mf][0] = rna_bits(A[(rb + g)     * 20 + kk + t]);
                ah[grp][mf][1] = rna_bits(A[(rb + g + 8) * 20 + kk + t]);
                ah[grp][mf][2] = rna_bits(A[(rb + g)     * 20 + kk + t + 4]);
                ah[grp][mf][3] = rna_bits(A[(rb + g + 8) * 20 + kk + t + 4]);
            }
        }
        #pragma unroll
        for (int nf = 0; nf < 4; nf++) {
            int cb = wc * 4 + nf;
            float4 bf = *(const float4*)&B[(cb * 32 + lane) * 4];
            uint32_t b0[2] = {__float_as_uint(bf.x), __float_as_uint(bf.y)};
            uint32_t b1[2] = {__float_as_uint(bf.z), __float_as_uint(bf.w)};
            #pragma unroll
            for (int mf = 0; mf < 4; mf++) {
                mma_tf32(acc[mf][nf], ah[0][mf], b0);
                mma_tf32(acc[mf][nf], ah[1][mf], b1);
            }
        }
        if (kb + 2 < 16) {
            int kn = kb + 2;
            IN_LOAD(kn, kn % 3);
        }
    }
    #undef IN_LOAD

    if (col0 < HP) {
        // Q region (tiles never straddle: HP % 128 == 0)
        #pragma unroll
        for (int mf = 0; mf < 4; mf++) {
            #pragma unroll
            for (int nf = 0; nf < 4; nf++) {
                #pragma unroll
                for (int cc = 0; cc < 2; cc++) {
                    int col = col0 + wc * 32 + nf * 8 + t * 2 + cc;
                    if (col < H) {
                        size_t base = ((size_t)b * H + col) * NTOK + nbase + wr * 64 + mf * 16 + g;
                        g_q[base]     = acc[mf][nf][cc];
                        g_q[base + 8] = acc[mf][nf][cc + 2];
                    }
                }
            }
        }
    } else {
        // KV region: thread's two adjacent cols are (k_h, v_h) of same h
        #pragma unroll
        for (int mf = 0; mf < 4; mf++) {
            #pragma unroll
            for (int nf = 0; nf < 4; nf++) {
                int h = ((col0 - HP) >> 1) + wc * 16 + nf * 4 + t;
                if (h < H) {
                    size_t base = ((size_t)b * H + h) * NTOK + nbase + wr * 64 + mf * 16 + g;
                    g_kv[base]     = acc[mf][nf][0] * acc[mf][nf][1];
                    g_kv[base + 8] = acc[mf][nf][2] * acc[mf][nf][3];
                }
            }
        }
    }
}

// ---------------------------------------------------------------------------
// Wo GEMM + residual: g_h[R,256] += G[R,H] @ Wo[H,256].
// Tile 128x128, kstep 16, 1-term tf32 B, 3-stage ring, loads after MMAs.
// A rows past H clamped (they multiply zero-padded WoF columns -> 0).
// ---------------------------------------------------------------------------
__global__ void __launch_bounds__(256, 2) gemm_out(int H)
{
    __shared__ __align__(16) float shA[3][16 * 136];
    __shared__ __align__(16) float shB[3][16 * 32 * 4];

    int tid = threadIdx.x;
    int row0 = blockIdx.y * 128;
    int col0 = blockIdx.x * 128;
    int b = row0 >> 10;
    int nbase = row0 & (NTOK - 1);
    int cb0 = col0 >> 3;

    int wid = tid >> 5, lane = tid & 31;
    int g = lane >> 2, t = lane & 3;
    int wr = wid >> 2, wc = wid & 3;

    float acc[4][4][4] = {};

    int akk = tid >> 5, aseg = tid & 31;   // akk 0..7, two i-iters cover k 0..15

    #define OUT_LOAD(kb, st)                                                     \
    {                                                                            \
        _Pragma("unroll")                                                        \
        for (int i = 0; i < 2; i++) {                                            \
            int k = akk + i * 8;                                                 \
            int krow = (kb) * 16 + k;                                            \
            if (krow > H - 1) krow = H - 1;                                      \
            cp16(sAddr(&shA[st][k * 136 + aseg * 4]),                            \
                 &g_q[((size_t)b * H + krow) * NTOK + nbase + aseg * 4]);        \
        }                                                                        \
        _Pragma("unroll")                                                        \
        for (int i = 0; i < 2; i++) {                                            \
            int c = i * 256 + tid;                                               \
            int cb = c >> 5, ln = c & 31;                                        \
            cp16(sAddr(&shB[st][(cb * 32 + ln) * 4]),                            \
                 &g_WoF[kb][cb0 + cb][ln][0]);                                   \
        }                                                                        \
        CP_COMMIT();                                                             \
    }

    int ksteps = (H + 15) >> 4;   // 23 or 10
    OUT_LOAD(0, 0);
    OUT_LOAD(1, 1);

    for (int kb = 0; kb < ksteps; kb++) {
        if (kb == ksteps - 1) { CP_WAIT0(); } else { CP_WAIT1(); }
        __syncthreads();
        int st = kb % 3;
        const float* A = shA[st];
        const float* B = shB[st];

        uint32_t ah[2][4][4];
        #pragma unroll
        for (int grp = 0; grp < 2; grp++) {
            int kk = grp * 8;
            #pragma unroll
            for (int mf = 0; mf < 4; mf++) {
                int rb = wr * 64 + mf * 16;
                ah[grp][mf][0] = __float_as_uint(A[(kk + t)     * 136 + rb + g]);
                ah[grp][mf][1] = __float_as_uint(A[(kk + t)     * 136 + rb + g + 8]);
                ah[grp][mf][2] = __float_as_uint(A[(kk + t + 4) * 136 + rb + g]);
                ah[grp][mf][3] = __float_as_uint(A[(kk + t + 4) * 136 + rb + g + 8]);
            }
        }
        #pragma unroll
        for (int nf = 0; nf < 4; nf++) {
            int cb = wc * 4 + nf;
            float4 bf = *(const float4*)&B[(cb * 32 + lane) * 4];
            uint32_t b0[2] = {__float_as_uint(bf.x), __float_as_uint(bf.y)};
            uint32_t b1[2] = {__float_as_uint(bf.z), __float_as_uint(bf.w)};
            #pragma unroll
            for (int mf = 0; mf < 4; mf++) {
                mma_tf32(acc[mf][nf], ah[0][mf], b0);
                mma_tf32(acc[mf][nf], ah[1][mf], b1);
            }
        }
        if (kb + 2 < ksteps) {
            int kn = kb + 2;
            OUT_LOAD(kn, kn % 3);
        }
    }
    #undef OUT_LOAD

    #pragma unroll
    for (int mf = 0; mf < 4; mf++) {
        #pragma unroll
        for (int nf = 0; nf < 4; nf++) {
            int col = col0 + wc * 32 + nf * 8 + t * 2;
            #pragma unroll
            for (int rr = 0; rr < 2; rr++) {
                int row = row0 + wr * 64 + mf * 16 + g + rr * 8;
                float2* hp = (float2*)&g_h[(size_t)row * DCH + col];
                float2 hv = *hp;
                hv.x += acc[mf][nf][rr * 2];
                hv.y += acc[mf][nf][rr * 2 + 1];
                *hp = hv;
            }
        }
    }
}

// ---------------------------------------------------------------------------
// 1024-pt radix-4 Stockham FFT, 256 threads, ping-pong, result in y.
// ---------------------------------------------------------------------------
template<bool INV>
__device__ __forceinline__ void fft1024(float2* x, float2* y, const float2* tw, int tid)
{
    float2* src = x;
    float2* dst = y;
    #pragma unroll
    for (int s = 0; s < 5; s++) {
        int m = 1 << (2 * s);
        float2 c0 = src[tid];
        float2 c1 = src[tid + 256];
        float2 c2 = src[tid + 512];
        float2 c3 = src[tid + 768];
        float2 t0 = cadd(c0, c2);
        float2 t1 = csub(c0, c2);
        float2 t2 = cadd(c1, c3);
        float2 d  = csub(c1, c3);
        float2 t3 = INV ? make_float2(-d.y, d.x) : make_float2(d.y, -d.x);
        int jm = tid & ~(m - 1);
        float2 w1 = tw[jm];
        if (INV) w1.y = -w1.y;
        float2 w2 = cmul(w1, w1);
        float2 w3 = cmul(w2, w1);
        int base = tid + 3 * jm;
        dst[base]         = cadd(t0, t2);
        dst[base + m]     = cmul(w1, cadd(t1, t3));
        dst[base + 2 * m] = cmul(w2, csub(t0, t2));
        dst[base + 3 * m] = cmul(w3, csub(t1, t3));
        __syncthreads();
        float2* tmp = src; src = dst; dst = tmp;
    }
}

__global__ void fft_filt_kernel(const float* __restrict__ filt, int H)
{
    int h = blockIdx.x;
    int tid = threadIdx.x;
    __shared__ float2 bufA[1024];
    __shared__ float2 bufB[1024];
    __shared__ float2 tw[256];
    {
        float ang = -6.283185307179586f * (float)tid / 1024.f;
        float sn, cs;
        sincosf(ang, &sn, &cs);
        tw[tid] = make_float2(cs, sn);
    }
    for (int n = tid; n < 1024; n += 256)
        bufA[n] = make_float2(filt[(size_t)n * H + h], 0.f);
    __syncthreads();
    fft1024<false>(bufA, bufB, tw, tid);
    for (int f = tid; f < 1024; f += 256)
        g_Ff[h * 1024 + f] = bufB[f];
}

// Packed-pair conv: reads kv directly, gates with q, writes tf32-rounded.
__global__ void conv_kernel(int H)
{
    int h = blockIdx.x;
    int b0 = blockIdx.y * 2, b1 = b0 + 1;
    int tid = threadIdx.x;
    __shared__ float2 bufA[1024];
    __shared__ float2 bufB[1024];
    __shared__ float2 tw[256];
    {
        float ang = -6.283185307179586f * (float)tid / 1024.f;
        float sn, cs;
        sincosf(ang, &sn, &cs);
        tw[tid] = make_float2(cs, sn);
    }

    const float* kv0 = &g_kv[((size_t)b0 * H + h) * NTOK];
    const float* kv1 = &g_kv[((size_t)b1 * H + h) * NTOK];
    float* qp0 = &g_q[((size_t)b0 * H + h) * NTOK];
    float* qp1 = &g_q[((size_t)b1 * H + h) * NTOK];

    {
        float4 u = *(const float4*)&kv0[tid * 4];
        float4 v = *(const float4*)&kv1[tid * 4];
        bufA[tid * 4 + 0] = make_float2(u.x, v.x);
        bufA[tid * 4 + 1] = make_float2(u.y, v.y);
        bufA[tid * 4 + 2] = make_float2(u.z, v.z);
        bufA[tid * 4 + 3] = make_float2(u.w, v.w);
    }
    __syncthreads();
    fft1024<false>(bufA, bufB, tw, tid);

    const float2* Fh = &g_Ff[h * 1024];
    for (int k = tid; k <= 512; k += 256) {
        int nk = (1024 - k) & 1023;
        float2 Z = bufB[k];
        float2 Y = bufB[nk];
        float Ar = 0.5f * (Z.x + Y.x), Ai = 0.5f * (Z.y - Y.y);
        float Br = 0.5f * (Z.y + Y.y), Bi = 0.5f * (Y.x - Z.x);
        float2 F = Fh[k];
        float P1r = Ar * F.x - Ai * F.y, P1i = Ar * F.y + Ai * F.x;
        float P2r = Br * F.x - Bi * F.y, P2i = Br * F.y + Bi * F.x;
        bufA[k] = make_float2(P1r - P2i, P1i + P2r);
        if (k != 0 && k != 512)
            bufA[nk] = make_float2(P1r + P2i, -P1i + P2r);
    }
    __syncthreads();
    fft1024<true>(bufA, bufB, tw, tid);

    const float inv = 1.f / 1024.f;
    {
        float4 q0 = *(const float4*)&qp0[tid * 4];
        float4 q1 = *(const float4*)&qp1[tid * 4];
        float2 c0 = bufB[tid * 4 + 0];
        float2 c1 = bufB[tid * 4 + 1];
        float2 c2 = bufB[tid * 4 + 2];
        float2 c3 = bufB[tid * 4 + 3];
        q0.x = tf32_rna_f(q0.x * c0.x * inv);
        q0.y = tf32_rna_f(q0.y * c1.x * inv);
        q0.z = tf32_rna_f(q0.z * c2.x * inv);
        q0.w = tf32_rna_f(q0.w * c3.x * inv);
        q1.x = tf32_rna_f(q1.x * c0.y * inv);
        q1.y = tf32_rna_f(q1.y * c1.y * inv);
        q1.z = tf32_rna_f(q1.z * c2.y * inv);
        q1.w = tf32_rna_f(q1.w * c3.y * inv);
        *(float4*)&qp0[tid * 4] = q0;
        *(float4*)&qp1[tid * 4] = q1;
    }
}

// ---------------------------------------------------------------------------
// reg_linear + BN partials: 32 tokens per block
// ---------------------------------------------------------------------------
__global__ void __launch_bounds__(256) reglin_kernel(const float* __restrict__ Wm0,
                                                     const float* __restrict__ Wm1)
{
    __shared__ float W0[64 * 64];
    __shared__ float W1[64 * 64];
    __shared__ __align__(16) float hs[8 * 256];
    __shared__ float red0[256], red1[256];
    int tid = threadIdx.x;
    int row0 = blockIdx.x * 32;
    for (int i = tid; i < 4096; i += 256) { W0[i] = Wm0[i]; W1[i] = Wm1[i]; }
    int k = tid & 63, grp = tid >> 6;
    float ls0 = 0.f, ls1 = 0.f;
    for (int batch = 0; batch < 4; batch++) {
        __syncthreads();
        for (int i = tid; i < 2048; i += 256)
            hs[i] = g_h[(size_t)(row0 + batch * 8) * DCH + i];
        __syncthreads();
        #pragma unroll
        for (int tt = 0; tt < 2; tt++) {
            int t = grp * 2 + tt;
            const float* hr = &hs[t * 256];
            float s = 0.f, v0 = 0.f, v1 = 0.f, v2 = 0.f;
            #pragma unroll 8
            for (int m = 0; m < 64; m++) {
                float4 hv = *(const float4*)&hr[m * 4];
                float w0 = W0[m * 64 + k];
                float w1 = W1[m * 64 + k];
                s  += hv.x * w0;
                v0 += hv.y * w1;
                v1 += hv.z * w1;
                v2 += hv.w * w1;
            }
            *(float4*)&g_y[(size_t)(row0 + batch * 8 + t) * DCH + k * 4] = make_float4(s, v0, v1, v2);
            ls0 += s * s;
            ls1 += v0 * v0 + v1 * v1 + v2 * v2;
        }
    }
    red0[tid] = ls0; red1[tid] = ls1;
    __syncthreads();
    if (grp == 0) {
        float t0 = red0[k] + red0[64 + k] + red0[128 + k] + red0[192 + k];
        float t1 = red1[k] + red1[64 + k] + red1[128 + k] + red1[192 + k];
        g_part0[k * NBLK2 + blockIdx.x] = t0;
        g_part1[k * NBLK2 + blockIdx.x] = t1;
    }
}

__global__ void scale_red_kernel(const float* __restrict__ g0, const float* __restrict__ g1)
{
    int c = blockIdx.x;          // 0..127
    int ch = c & 63;
    const float* src = (c < 64) ? &g_part0[(size_t)ch * NBLK2] : &g_part1[(size_t)ch * NBLK2];
    int tid = threadIdx.x;
    float s = 0.f;
    for (int i = tid; i < NBLK2; i += 256) s += src[i];
    __shared__ float red[256];
    red[tid] = s;
    __syncthreads();
    for (int st = 128; st; st >>= 1) {
        if (tid < st) red[tid] += red[tid + st];
        __syncthreads();
    }
    if (tid == 0) {
        float norm = sqrtf(red[0] / (float)RTOT + EPSF);
        if (c < 64) g_scale0[ch] = g0[ch] / norm;
        else        g_scale1[ch] = g1[ch] / norm;
    }
}

__global__ void actres_kernel()
{
    size_t idx = (size_t)blockIdx.x * 256 + threadIdx.x;
    int m = (int)(idx & 63);
    float4 yv = *(float4*)&g_y[idx * 4];
    float s  = yv.x * g_scale0[m];
    float sc = g_scale1[m];
    float v0 = yv.y * sc, v1 = yv.z * sc, v2 = yv.w * sc;
    float sg  = 1.f / (1.f + __expf(-fabsf(s)));
    float vn  = sqrtf(v0 * v0 + v1 * v1 + v2 * v2 + EPSF);
    float sgv = 1.f / (1.f + __expf(-vn));
    float4* hp = (float4*)&g_h[idx * 4];
    float4 hv = *hp;
    hv.x += s * sg;
    hv.y += v0 * sgv;
    hv.z += v1 * sgv;
    hv.w += v2 * sgv;
    *hp = hv;
}

__global__ void pool_kernel(const float* __restrict__ w_out, float* __restrict__ out)
{
    int b = blockIdx.x;
    int tid = threadIdx.x;
    __shared__ float wsh[64];
    if (tid < 64) wsh[tid] = w_out[tid];
    __syncthreads();
    float a0 = 0.f, a1 = 0.f, a2 = 0.f;
    for (int n = tid; n < NTOK; n += 256) {
        const float* hr = &g_h[((size_t)b * NTOK + n) * DCH];
        #pragma unroll 8
        for (int m = 0; m < 64; m++) {
            float w = wsh[m];
            float4 hv = *(const float4*)&hr[m * 4];
            a0 += hv.y * w;
            a1 += hv.z * w;
            a2 += hv.w * w;
        }
    }
    __shared__ float r0[256], r1[256], r2[256];
    r0[tid] = a0; r1[tid] = a1; r2[tid] = a2;
    __syncthreads();
    for (int st = 128; st; st >>= 1) {
        if (tid < st) { r0[tid] += r0[tid + st]; r1[tid] += r1[tid + st]; r2[tid] += r2[tid + st]; }
        __syncthreads();
    }
    if (tid == 0) {
        out[b * 3 + 0] = r0[0] / (float)NTOK;
        out[b * 3 + 1] = r1[0] / (float)NTOK;
        out[b * 3 + 2] = r2[0] / (float)NTOK;
    }
}

// ---------------------------------------------------------------------------
extern "C" void kernel_launch(void* const* d_in, const int* in_sizes, int n_in,
                              void* d_out, int out_size)
{
    (void)in_sizes; (void)n_in; (void)out_size;
    const float* x       = (const float*)d_in[0];
    const float* tok_emb = (const float*)d_in[1];
    const float* Wf      = (const float*)d_in[2];
    const float* wv      = (const float*)d_in[3];
    const float* w_out   = (const float*)d_in[4];
    const int Hs[3] = {360, 360, 160};

    init_h_kernel<<<NTOK, 256>>>(x, tok_emb, Wf, wv);

    for (int L = 0; L < 3; L++) {
        int base = 5 + L * 9;
        const float* Wq   = (const float*)d_in[base + 0];
        const float* Wk   = (const float*)d_in[base + 1];
        const float* Wvw  = (const float*)d_in[base + 2];
        const float* filt = (const float*)d_in[base + 3];
        const float* Wo   = (const float*)d_in[base + 4];
        const float* Wm0  = (const float*)d_in[base + 5];
        const float* Wm1  = (const float*)d_in[base + 6];
        const float* g0   = (const float*)d_in[base + 7];
        const float* g1   = (const float*)d_in[base + 8];
        int H = Hs[L];

        if (H > 256) {
            presplit_cat<384><<<256 * 3 * 384 / 256, 256>>>(Wq, Wk, Wvw, H);
            gemm_in<384><<<dim3(3 * 384 / 128, RTOT / 128), 256>>>(H);
        } else {
            presplit_cat<256><<<256 * 3 * 256 / 256, 256>>>(Wq, Wk, Wvw, H);
            gemm_in<256><<<dim3(3 * 256 / 128, RTOT / 128), 256>>>(H);
        }
        presplit_wo<<<HPADMAX * DCH / 256, 256>>>(Wo, H);
        fft_filt_kernel<<<H, 256>>>(filt, H);
        conv_kernel<<<dim3(H, BSZ / 2), 256>>>(H);
        gemm_out<<<dim3(DCH / 128, RTOT / 128), 256>>>(H);
        reglin_kernel<<<NBLK2, 256>>>(Wm0, Wm1);
        scale_red_kernel<<<128, 256>>>(g0, g1);
        actres_kernel<<<RTOT * 64 / 256, 256>>>();
    }

    pool_kernel<<<BSZ, 256>>>(w_out, (float*)d_out);
}

// round 13
// speedup vs baseline: 1.3816x; 1.0027x over previous
#include <cuda_runtime.h>
#include <math.h>
#include <stdint.h>

// Problem constants
#define BSZ   64
#define NTOK  1024
#define MCH   64
#define DCH   256       // 4*M
#define PDIM  64
#define RTOT  (BSZ*NTOK)   // 65536
#define HMAX  360
#define HPADMAX 384
#define EPSF  1e-5f
#define NBLK2 (RTOT/32)    // 2048 reglin blocks

// -------- scratch (static __device__ globals) --------
__device__ __align__(16) float g_h[(size_t)RTOT*DCH];
__device__ __align__(16) float g_y[(size_t)RTOT*DCH];
__device__ __align__(16) float g_q[(size_t)BSZ*HMAX*NTOK];
__device__ __align__(16) float g_kv[(size_t)BSZ*HMAX*NTOK];
__device__ __align__(16) float2 g_Ff[HMAX*NTOK];
// fragment-packed weights, 1-term tf32, k16 granularity:
// [kb16][cb][lane][4 words: g0w0, g0w1, g1w0, g1w1]
__device__ __align__(16) float g_WcF[16][3*HPADMAX/8][32][4];
__device__ __align__(16) float g_WoF[HPADMAX/16][32][32][4];
__device__ float g_part0[MCH*NBLK2];
__device__ float g_part1[MCH*NBLK2];
__device__ float g_scale0[MCH];
__device__ float g_scale1[MCH];

// ---------------------------------------------------------------------------
__device__ __forceinline__ void mma_tf32(float* c, const uint32_t* a, const uint32_t* b)
{
    asm volatile(
        "mma.sync.aligned.m16n8k8.row.col.f32.tf32.tf32.f32 "
        "{%0,%1,%2,%3}, {%4,%5,%6,%7}, {%8,%9}, {%0,%1,%2,%3};\n"
        : "+f"(c[0]), "+f"(c[1]), "+f"(c[2]), "+f"(c[3])
        : "r"(a[0]), "r"(a[1]), "r"(a[2]), "r"(a[3]), "r"(b[0]), "r"(b[1]));
}

__device__ __forceinline__ float tf32_rna_f(float x)
{
    uint32_t r;
    asm("cvt.rna.tf32.f32 %0, %1;" : "=r"(r) : "f"(x));
    return __uint_as_float(r);
}
__device__ __forceinline__ uint32_t rna_bits(float x)
{
    uint32_t r;
    asm("cvt.rna.tf32.f32 %0, %1;" : "=r"(r) : "f"(x));
    return r;
}

__device__ __forceinline__ uint32_t sAddr(const void* p)
{
    return (uint32_t)__cvta_generic_to_shared(p);
}
__device__ __forceinline__ void cp16(uint32_t dst, const void* src)
{
    asm volatile("cp.async.cg.shared.global [%0], [%1], 16;\n" :: "r"(dst), "l"(src));
}
#define CP_COMMIT() asm volatile("cp.async.commit_group;\n")
#define CP_WAIT1()  asm volatile("cp.async.wait_group 1;\n")
#define CP_WAIT0()  asm volatile("cp.async.wait_group 0;\n")

__device__ __forceinline__ float2 cmul(float2 a, float2 b)
{ return make_float2(a.x*b.x - a.y*b.y, a.x*b.y + a.y*b.x); }
__device__ __forceinline__ float2 cadd(float2 a, float2 b){ return make_float2(a.x+b.x, a.y+b.y); }
__device__ __forceinline__ float2 csub(float2 a, float2 b){ return make_float2(a.x-b.x, a.y-b.y); }

// ---------------------------------------------------------------------------
// init h (fp32 residual stream — NEVER rounded)
// ---------------------------------------------------------------------------
__global__ void init_h_kernel(const float* __restrict__ x,
                              const float* __restrict__ tok_emb,
                              const float* __restrict__ Wf,
                              const float* __restrict__ wv)
{
    int n = blockIdx.x;
    int tid = threadIdx.x;   // 256
    __shared__ float f[PDIM];
    __shared__ float s0[MCH];
    if (tid < PDIM) {
        int p = tid;
        int j2 = p & ~1;
        float div = expf(-logf(10000.0f) * (float)j2 / (float)PDIM);
        float ang = (float)n * div;
        float pe = (p & 1) ? cosf(ang) : sinf(ang);
        int tt = (n == NTOK - 1) ? 2 : (n & 1);
        f[p] = pe + tok_emb[tt * PDIM + p];
    }
    __syncthreads();
    if (tid < MCH) {
        float acc = 0.f;
        #pragma unroll 8
        for (int p = 0; p < PDIM; p++) acc += f[p] * Wf[p * MCH + tid];
        s0[tid] = acc;
    }
    __syncthreads();
    int m = tid >> 2, r = tid & 3;
    float wvm = wv[m];
    float sv = s0[m];
    for (int b = 0; b < BSZ; b++) {
        float val;
        if (r == 0) val = sv;
        else        val = x[((size_t)b * NTOK + n) * 3 + (r - 1)] * wvm;
        g_h[((size_t)b * NTOK + n) * DCH + tid] = val;
    }
}

// ---------------------------------------------------------------------------
// weight pre-split (1-term RNA tf32). Column map over 3*HP:
//   c < HP  -> Wq column c
//   c >= HP -> j=c-HP; h=j>>1; even j -> Wk[h], odd j -> Wv[h]
// ---------------------------------------------------------------------------
template<int HP>
__global__ void presplit_cat(const float* __restrict__ Wq,
                             const float* __restrict__ Wk,
                             const float* __restrict__ Wv2, int H)
{
    int idx = blockIdx.x * 256 + threadIdx.x;   // over 256 * 3*HP
    int k = idx / (3 * HP), c = idx % (3 * HP);
    const float* W;
    int h;
    if (c < HP) { W = Wq; h = c; }
    else {
        int j = c - HP;
        h = j >> 1;
        W = (j & 1) ? Wv2 : Wk;
    }
    int kb = k >> 4, kk = k & 15;
    int grp = kk >> 3, kk8 = kk & 7;
    int t = kk8 & 3, pos = kk8 >> 2;
    int cb = c >> 3, lane = (c & 7) * 4 + t;
    float w = (h < H) ? W[(size_t)k * H + h] : 0.f;
    g_WcF[kb][cb][lane][grp * 2 + pos] = tf32_rna_f(w);
}

__global__ void presplit_wo(const float* __restrict__ Wo, int H)
{
    int idx = blockIdx.x * 256 + threadIdx.x;   // over HPADMAX*256
    int k = idx >> 8, n = idx & 255;
    int kb = k >> 4, kk = k & 15;
    int grp = kk >> 3, kk8 = kk & 7;
    int t = kk8 & 3, pos = kk8 >> 2;
    int cb = n >> 3, lane = (n & 7) * 4 + t;
    float w = (k < H) ? Wo[(size_t)k * DCH + n] : 0.f;
    g_WoF[kb][cb][lane][grp * 2 + pos] = tf32_rna_f(w);
}

// ---------------------------------------------------------------------------
// Merged qkv GEMM: C[R, 3*HP] = A[R,256] @ Wcat. Tile 128x128, kstep 16,
// 1-term tf32 B, A rounded at fragment read (rna_bits).
// 3-stage cp.async ring distance 2, loads after MMAs.
// ---------------------------------------------------------------------------
template<int HP>
__global__ void __launch_bounds__(256, 2) gemm_in(int H)
{
    __shared__ __align__(16) float shA[3][128 * 20];        // [row][k16 pad 20]
    __shared__ __align__(16) float shB[3][16 * 32 * 4];     // one float4 per (cb,lane)

    int tid = threadIdx.x;
    int row0 = blockIdx.y * 128;
    int col0 = blockIdx.x * 128;        // over 3*HP
    int b = row0 >> 10;
    int nbase = row0 & (NTOK - 1);
    int cb0 = col0 >> 3;

    int wid = tid >> 5, lane = tid & 31;
    int g = lane >> 2, t = lane & 3;
    int wr = wid >> 2, wc = wid & 3;

    float acc[4][4][4] = {};

    int ar2 = tid >> 2, akq = tid & 3;

    #define IN_LOAD(kb, st)                                                   \
    {                                                                         \
        _Pragma("unroll")                                                     \
        for (int i = 0; i < 2; i++) {                                         \
            int row = ar2 + i * 64;                                           \
            cp16(sAddr(&shA[st][row * 20 + akq * 4]),                         \
                 &g_h[(size_t)(row0 + row) * DCH + (kb) * 16 + akq * 4]);     \
        }                                                                     \
        _Pragma("unroll")                                                     \
        for (int i = 0; i < 2; i++) {                                         \
            int c = i * 256 + tid;                                            \
            int cb = c >> 5, ln = c & 31;                                     \
            cp16(sAddr(&shB[st][(cb * 32 + ln) * 4]),                         \
                 &g_WcF[kb][cb0 + cb][ln][0]);                                \
        }                                                                     \
        CP_COMMIT();                                                          \
    }

    IN_LOAD(0, 0);
    IN_LOAD(1, 1);

    for (int kb = 0; kb < 16; kb++) {
        if (kb == 15) { CP_WAIT0(); } else { CP_WAIT1(); }
        __syncthreads();
        int st = kb % 3;
        const float* A = shA[st];
        const float* B = shB[st];

        // A fragments for both k8 groups (rounded at read)
        uint32_t ah[2][4][4];
        #pragma unroll
        for (int grp = 0; grp < 2; grp++) {
            int kk = grp * 8;
            #pragma unroll
            for (int mf = 0; mf < 4; mf++) {
                int rb = wr * 64 + mf * 16;
                ah[grp][mf][0] = rna_bits(A[(rb + g)     * 20 + kk + t]);
                ah[grp][mf][1] = rna_bits(A[(rb + g + 8) * 20 + kk + t]);
                ah[grp][mf][2] = rna_bits(A[(rb + g)     * 20 + kk + t + 4]);
                ah[grp][mf][3] = rna_bits(A[(rb + g + 8) * 20 + kk + t + 4]);
            }
        }
        #pragma unroll
        for (int nf = 0; nf < 4; nf++) {
            int cb = wc * 4 + nf;
            float4 bf = *(const float4*)&B[(cb * 32 + lane) * 4];
            uint32_t b0[2] = {__float_as_uint(bf.x), __float_as_uint(bf.y)};
            uint32_t b1[2] = {__float_as_uint(bf.z), __float_as_uint(bf.w)};
            #pragma unroll
            for (int mf = 0; mf < 4; mf++) {
                mma_tf32(acc[mf][nf], ah[0][mf], b0);
                mma_tf32(acc[mf][nf], ah[1][mf], b1);
            }
        }
        if (kb + 2 < 16) {
            int kn = kb + 2;
            IN_LOAD(kn, kn % 3);
        }
    }
    #undef IN_LOAD

    if (col0 < HP) {
        // Q region (tiles never straddle: HP % 128 == 0)
        #pragma unroll
        for (int mf = 0; mf < 4; mf++) {
            #pragma unroll
            for (int nf = 0; nf < 4; nf++) {
                #pragma unroll
                for (int cc = 0; cc < 2; cc++) {
                    int col = col0 + wc * 32 + nf * 8 + t * 2 + cc;
                    if (col < H) {
                        size_t base = ((size_t)b * H + col) * NTOK + nbase + wr * 64 + mf * 16 + g;
                        g_q[base]     = acc[mf][nf][cc];
                        g_q[base + 8] = acc[mf][nf][cc + 2];
                    }
                }
            }
        }
    } else {
        // KV region: thread's two adjacent cols are (k_h, v_h) of same h
        #pragma unroll
        for (int mf = 0; mf < 4; mf++) {
            #pragma unroll
            for (int nf = 0; nf < 4; nf++) {
                int h = ((col0 - HP) >> 1) + wc * 16 + nf * 4 + t;
                if (h < H) {
                    size_t base = ((size_t)b * H + h) * NTOK + nbase + wr * 64 + mf * 16 + g;
                    g_kv[base]     = acc[mf][nf][0] * acc[mf][nf][1];
                    g_kv[base + 8] = acc[mf][nf][2] * acc[mf][nf][3];
                }
            }
        }
    }
}

// ---------------------------------------------------------------------------
// Wo GEMM + residual: g_h[R,256] += G[R,H] @ Wo[H,256].
// Tile 128x128, kstep 16, 1-term tf32, 3-stage ring, loads after MMAs.
// A rows past H clamped (multiply zero-padded WoF columns -> 0).
// ---------------------------------------------------------------------------
__global__ void __launch_bounds__(256, 2) gemm_out(int H)
{
    __shared__ __align__(16) float shA[3][16 * 136];
    __shared__ __align__(16) float shB[3][16 * 32 * 4];

    int tid = threadIdx.x;
    int row0 = blockIdx.y * 128;
    int col0 = blockIdx.x * 128;
    int b = row0 >> 10;
    int nbase = row0 & (NTOK - 1);
    int cb0 = col0 >> 3;

    int wid = tid >> 5, lane = tid & 31;
    int g = lane >> 2, t = lane & 3;
    int wr = wid >> 2, wc = wid & 3;

    float acc[4][4][4] = {};

    int akk = tid >> 5, aseg = tid & 31;

    #define OUT_LOAD(kb, st)                                                     \
    {                                                                            \
        _Pragma("unroll")                                                        \
        for (int i = 0; i < 2; i++) {                                            \
            int k = akk + i * 8;                                                 \
            int krow = (kb) * 16 + k;                                            \
            if (krow > H - 1) krow = H - 1;                                      \
            cp16(sAddr(&shA[st][k * 136 + aseg * 4]),                            \
                 &g_q[((size_t)b * H + krow) * NTOK + nbase + aseg * 4]);        \
        }                                                                        \
        _Pragma("unroll")                                                        \
        for (int i = 0; i < 2; i++) {                                            \
            int c = i * 256 + tid;                                               \
            int cb = c >> 5, ln = c & 31;                                        \
            cp16(sAddr(&shB[st][(cb * 32 + ln) * 4]),                            \
                 &g_WoF[kb][cb0 + cb][ln][0]);                                   \
        }                                                                        \
        CP_COMMIT();                                                             \
    }

    int ksteps = (H + 15) >> 4;   // 23 or 10
    OUT_LOAD(0, 0);
    OUT_LOAD(1, 1);

    for (int kb = 0; kb < ksteps; kb++) {
        if (kb == ksteps - 1) { CP_WAIT0(); } else { CP_WAIT1(); }
        __syncthreads();
        int st = kb % 3;
        const float* A = shA[st];
        const float* B = shB[st];

        uint32_t ah[2][4][4];
        #pragma unroll
        for (int grp = 0; grp < 2; grp++) {
            int kk = grp * 8;
            #pragma unroll
            for (int mf = 0; mf < 4; mf++) {
                int rb = wr * 64 + mf * 16;
                ah[grp][mf][0] = __float_as_uint(A[(kk + t)     * 136 + rb + g]);
                ah[grp][mf][1] = __float_as_uint(A[(kk + t)     * 136 + rb + g + 8]);
                ah[grp][mf][2] = __float_as_uint(A[(kk + t + 4) * 136 + rb + g]);
                ah[grp][mf][3] = __float_as_uint(A[(kk + t + 4) * 136 + rb + g + 8]);
            }
        }
        #pragma unroll
        for (int nf = 0; nf < 4; nf++) {
            int cb = wc * 4 + nf;
            float4 bf = *(const float4*)&B[(cb * 32 + lane) * 4];
            uint32_t b0[2] = {__float_as_uint(bf.x), __float_as_uint(bf.y)};
            uint32_t b1[2] = {__float_as_uint(bf.z), __float_as_uint(bf.w)};
            #pragma unroll
            for (int mf = 0; mf < 4; mf++) {
                mma_tf32(acc[mf][nf], ah[0][mf], b0);
                mma_tf32(acc[mf][nf], ah[1][mf], b1);
            }
        }
        if (kb + 2 < ksteps) {
            int kn = kb + 2;
            OUT_LOAD(kn, kn % 3);
        }
    }
    #undef OUT_LOAD

    #pragma unroll
    for (int mf = 0; mf < 4; mf++) {
        #pragma unroll
        for (int nf = 0; nf < 4; nf++) {
            int col = col0 + wc * 32 + nf * 8 + t * 2;
            #pragma unroll
            for (int rr = 0; rr < 2; rr++) {
                int row = row0 + wr * 64 + mf * 16 + g + rr * 8;
                float2* hp = (float2*)&g_h[(size_t)row * DCH + col];
                float2 hv = *hp;
                hv.x += acc[mf][nf][rr * 2];
                hv.y += acc[mf][nf][rr * 2 + 1];
                *hp = hv;
            }
        }
    }
}

// ---------------------------------------------------------------------------
// 1024-pt radix-4 Stockham FFT, 256 worker lanes (ltid), ping-pong, result in y.
// Block-wide __syncthreads; must be called uniformly by all threads.
// ---------------------------------------------------------------------------
template<bool INV>
__device__ __forceinline__ void fft1024(float2* x, float2* y, const float2* tw, int ltid)
{
    float2* src = x;
    float2* dst = y;
    #pragma unroll
    for (int s = 0; s < 5; s++) {
        int m = 1 << (2 * s);
        float2 c0 = src[ltid];
        float2 c1 = src[ltid + 256];
        float2 c2 = src[ltid + 512];
        float2 c3 = src[ltid + 768];
        float2 t0 = cadd(c0, c2);
        float2 t1 = csub(c0, c2);
        float2 t2 = cadd(c1, c3);
        float2 d  = csub(c1, c3);
        float2 t3 = INV ? make_float2(-d.y, d.x) : make_float2(d.y, -d.x);
        int jm = ltid & ~(m - 1);
        float2 w1 = tw[jm];
        if (INV) w1.y = -w1.y;
        float2 w2 = cmul(w1, w1);
        float2 w3 = cmul(w2, w1);
        int base = ltid + 3 * jm;
        dst[base]         = cadd(t0, t2);
        dst[base + m]     = cmul(w1, cadd(t1, t3));
        dst[base + 2 * m] = cmul(w2, csub(t0, t2));
        dst[base + 3 * m] = cmul(w3, csub(t1, t3));
        __syncthreads();
        float2* tmp = src; src = dst; dst = tmp;
    }
}

__global__ void fft_filt_kernel(const float* __restrict__ filt, int H)
{
    int h = blockIdx.x;
    int tid = threadIdx.x;
    __shared__ float2 bufA[1024];
    __shared__ float2 bufB[1024];
    __shared__ float2 tw[256];
    {
        float ang = -6.283185307179586f * (float)tid / 1024.f;
        float sn, cs;
        sincosf(ang, &sn, &cs);
        tw[tid] = make_float2(cs, sn);
    }
    for (int n = tid; n < 1024; n += 256)
        bufA[n] = make_float2(filt[(size_t)n * H + h], 0.f);
    __syncthreads();
    fft1024<false>(bufA, bufB, tw, tid);
    for (int f = tid; f < 1024; f += 256)
        g_Ff[h * 1024 + f] = bufB[f];
}

// Packed-pair conv, TWO h per block (512 threads; fid selects FFT group).
// Reads kv, gates with q, writes tf32-rounded result in place of q
// (q is a GEMM operand copy, not the residual stream — rounding allowed).
__global__ void __launch_bounds__(512) conv_kernel(int H)
{
    int tid = threadIdx.x;
    int fid = tid >> 8;          // 0 or 1
    int ltid = tid & 255;
    int h = blockIdx.x * 2 + fid;
    int b0 = blockIdx.y * 2, b1 = b0 + 1;

    __shared__ float2 bufA[2][1024];
    __shared__ float2 bufB[2][1024];
    __shared__ float2 tw[256];
    if (fid == 0) {
        float ang = -6.283185307179586f * (float)ltid / 1024.f;
        float sn, cs;
        sincosf(ang, &sn, &cs);
        tw[ltid] = make_float2(cs, sn);
    }

    const float* kv0 = &g_kv[((size_t)b0 * H + h) * NTOK];
    const float* kv1 = &g_kv[((size_t)b1 * H + h) * NTOK];
    float* qp0 = &g_q[((size_t)b0 * H + h) * NTOK];
    float* qp1 = &g_q[((size_t)b1 * H + h) * NTOK];

    {
        float4 u = *(const float4*)&kv0[ltid * 4];
        float4 v = *(const float4*)&kv1[ltid * 4];
        bufA[fid][ltid * 4 + 0] = make_float2(u.x, v.x);
        bufA[fid][ltid * 4 + 1] = make_float2(u.y, v.y);
        bufA[fid][ltid * 4 + 2] = make_float2(u.z, v.z);
        bufA[fid][ltid * 4 + 3] = make_float2(u.w, v.w);
    }
    __syncthreads();
    fft1024<false>(bufA[fid], bufB[fid], tw, ltid);

    const float2* Fh = &g_Ff[h * 1024];
    for (int k = ltid; k <= 512; k += 256) {
        int nk = (1024 - k) & 1023;
        float2 Z = bufB[fid][k];
        float2 Y = bufB[fid][nk];
        float Ar = 0.5f * (Z.x + Y.x), Ai = 0.5f * (Z.y - Y.y);
        float Br = 0.5f * (Z.y + Y.y), Bi = 0.5f * (Y.x - Z.x);
        float2 F = Fh[k];
        float P1r = Ar * F.x - Ai * F.y, P1i = Ar * F.y + Ai * F.x;
        float P2r = Br * F.x - Bi * F.y, P2i = Br * F.y + Bi * F.x;
        bufA[fid][k] = make_float2(P1r - P2i, P1i + P2r);
        if (k != 0 && k != 512)
            bufA[fid][nk] = make_float2(P1r + P2i, -P1i + P2r);
    }
    __syncthreads();
    fft1024<true>(bufA[fid], bufB[fid], tw, ltid);

    const float inv = 1.f / 1024.f;
    {
        float4 q0 = *(const float4*)&qp0[ltid * 4];
        float4 q1 = *(const float4*)&qp1[ltid * 4];
        float2 c0 = bufB[fid][ltid * 4 + 0];
        float2 c1 = bufB[fid][ltid * 4 + 1];
        float2 c2 = bufB[fid][ltid * 4 + 2];
        float2 c3 = bufB[fid][ltid * 4 + 3];
        q0.x = tf32_rna_f(q0.x * c0.x * inv);
        q0.y = tf32_rna_f(q0.y * c1.x * inv);
        q0.z = tf32_rna_f(q0.z * c2.x * inv);
        q0.w = tf32_rna_f(q0.w * c3.x * inv);
        q1.x = tf32_rna_f(q1.x * c0.y * inv);
        q1.y = tf32_rna_f(q1.y * c1.y * inv);
        q1.z = tf32_rna_f(q1.z * c2.y * inv);
        q1.w = tf32_rna_f(q1.w * c3.y * inv);
        *(float4*)&qp0[ltid * 4] = q0;
        *(float4*)&qp1[ltid * 4] = q1;
    }
}

// ---------------------------------------------------------------------------
// reg_linear + BN partials: 32 tokens per block
// ---------------------------------------------------------------------------
__global__ void __launch_bounds__(256) reglin_kernel(const float* __restrict__ Wm0,
                                                     const float* __restrict__ Wm1)
{
    __shared__ float W0[64 * 64];
    __shared__ float W1[64 * 64];
    __shared__ __align__(16) float hs[8 * 256];
    __shared__ float red0[256], red1[256];
    int tid = threadIdx.x;
    int row0 = blockIdx.x * 32;
    for (int i = tid; i < 4096; i += 256) { W0[i] = Wm0[i]; W1[i] = Wm1[i]; }
    int k = tid & 63, grp = tid >> 6;
    float ls0 = 0.f, ls1 = 0.f;
    for (int batch = 0; batch < 4; batch++) {
        __syncthreads();
        for (int i = tid; i < 2048; i += 256)
            hs[i] = g_h[(size_t)(row0 + batch * 8) * DCH + i];
        __syncthreads();
        #pragma unroll
        for (int tt = 0; tt < 2; tt++) {
            int t = grp * 2 + tt;
            const float* hr = &hs[t * 256];
            float s = 0.f, v0 = 0.f, v1 = 0.f, v2 = 0.f;
            #pragma unroll 8
            for (int m = 0; m < 64; m++) {
                float4 hv = *(const float4*)&hr[m * 4];
                float w0 = W0[m * 64 + k];
                float w1 = W1[m * 64 + k];
                s  += hv.x * w0;
                v0 += hv.y * w1;
                v1 += hv.z * w1;
                v2 += hv.w * w1;
            }
            *(float4*)&g_y[(size_t)(row0 + batch * 8 + t) * DCH + k * 4] = make_float4(s, v0, v1, v2);
            ls0 += s * s;
            ls1 += v0 * v0 + v1 * v1 + v2 * v2;
        }
    }
    red0[tid] = ls0; red1[tid] = ls1;
    __syncthreads();
    if (grp == 0) {
        float t0 = red0[k] + red0[64 + k] + red0[128 + k] + red0[192 + k];
        float t1 = red1[k] + red1[64 + k] + red1[128 + k] + red1[192 + k];
        g_part0[k * NBLK2 + blockIdx.x] = t0;
        g_part1[k * NBLK2 + blockIdx.x] = t1;
    }
}

__global__ void scale_red_kernel(const float* __restrict__ g0, const float* __restrict__ g1)
{
    int c = blockIdx.x;          // 0..127
    int ch = c & 63;
    const float* src = (c < 64) ? &g_part0[(size_t)ch * NBLK2] : &g_part1[(size_t)ch * NBLK2];
    int tid = threadIdx.x;
    float s = 0.f;
    for (int i = tid; i < NBLK2; i += 256) s += src[i];
    __shared__ float red[256];
    red[tid] = s;
    __syncthreads();
    for (int st = 128; st; st >>= 1) {
        if (tid < st) red[tid] += red[tid + st];
        __syncthreads();
    }
    if (tid == 0) {
        float norm = sqrtf(red[0] / (float)RTOT + EPSF);
        if (c < 64) g_scale0[ch] = g0[ch] / norm;
        else        g_scale1[ch] = g1[ch] / norm;
    }
}

// BN + act + residual (fp32 residual stream — never rounded)
__global__ void actres_kernel()
{
    size_t idx = (size_t)blockIdx.x * 256 + threadIdx.x;
    int m = (int)(idx & 63);
    float4 yv = *(float4*)&g_y[idx * 4];
    float s  = yv.x * g_scale0[m];
    float sc = g_scale1[m];
    float v0 = yv.y * sc, v1 = yv.z * sc, v2 = yv.w * sc;
    float sg  = 1.f / (1.f + __expf(-fabsf(s)));
    float vn  = sqrtf(v0 * v0 + v1 * v1 + v2 * v2 + EPSF);
    float sgv = 1.f / (1.f + __expf(-vn));
    float4* hp = (float4*)&g_h[idx * 4];
    float4 hv = *hp;
    hv.x += s * sg;
    hv.y += v0 * sgv;
    hv.z += v1 * sgv;
    hv.w += v2 * sgv;
    *hp = hv;
}

__global__ void pool_kernel(const float* __restrict__ w_out, float* __restrict__ out)
{
    int b = blockIdx.x;
    int tid = threadIdx.x;
    __shared__ float wsh[64];
    if (tid < 64) wsh[tid] = w_out[tid];
    __syncthreads();
    float a0 = 0.f, a1 = 0.f, a2 = 0.f;
    for (int n = tid; n < NTOK; n += 256) {
        const float* hr = &g_h[((size_t)b * NTOK + n) * DCH];
        #pragma unroll 8
        for (int m = 0; m < 64; m++) {
            float w = wsh[m];
            float4 hv = *(const float4*)&hr[m * 4];
            a0 += hv.y * w;
            a1 += hv.z * w;
            a2 += hv.w * w;
        }
    }
    __shared__ float r0[256], r1[256], r2[256];
    r0[tid] = a0; r1[tid] = a1; r2[tid] = a2;
    __syncthreads();
    for (int st = 128; st; st >>= 1) {
        if (tid < st) { r0[tid] += r0[tid + st]; r1[tid] += r1[tid + st]; r2[tid] += r2[tid + st]; }
        __syncthreads();
    }
    if (tid == 0) {
        out[b * 3 + 0] = r0[0] / (float)NTOK;
        out[b * 3 + 1] = r1[0] / (float)NTOK;
        out[b * 3 + 2] = r2[0] / (float)NTOK;
    }
}

// ---------------------------------------------------------------------------
extern "C" void kernel_launch(void* const* d_in, const int* in_sizes, int n_in,
                              void* d_out, int out_size)
{
    (void)in_sizes; (void)n_in; (void)out_size;
    const float* x       = (const float*)d_in[0];
    const float* tok_emb = (const float*)d_in[1];
    const float* Wf      = (const float*)d_in[2];
    const float* wv      = (const float*)d_in[3];
    const float* w_out   = (const float*)d_in[4];
    const int Hs[3] = {360, 360, 160};

    init_h_kernel<<<NTOK, 256>>>(x, tok_emb, Wf, wv);

    for (int L = 0; L < 3; L++) {
        int base = 5 + L * 9;
        const float* Wq   = (const float*)d_in[base + 0];
        const float* Wk   = (const float*)d_in[base + 1];
        const float* Wvw  = (const float*)d_in[base + 2];
        const float* filt = (const float*)d_in[base + 3];
        const float* Wo   = (const float*)d_in[base + 4];
        const float* Wm0  = (const float*)d_in[base + 5];
        const float* Wm1  = (const float*)d_in[base + 6];
        const float* g0   = (const float*)d_in[base + 7];
        const float* g1   = (const float*)d_in[base + 8];
        int H = Hs[L];

        if (H > 256) {
            presplit_cat<384><<<256 * 3 * 384 / 256, 256>>>(Wq, Wk, Wvw, H);
            gemm_in<384><<<dim3(3 * 384 / 128, RTOT / 128), 256>>>(H);
        } else {
            presplit_cat<256><<<256 * 3 * 256 / 256, 256>>>(Wq, Wk, Wvw, H);
            gemm_in<256><<<dim3(3 * 256 / 128, RTOT / 128), 256>>>(H);
        }
        presplit_wo<<<HPADMAX * DCH / 256, 256>>>(Wo, H);
        fft_filt_kernel<<<H, 256>>>(filt, H);
        conv_kernel<<<dim3(H / 2, BSZ / 2), 512>>>(H);
        gemm_out<<<dim3(DCH / 128, RTOT / 128), 256>>>(H);
        reglin_kernel<<<NBLK2, 256>>>(Wm0, Wm1);
        scale_red_kernel<<<128, 256>>>(g0, g1);
        actres_kernel<<<RTOT * 64 / 256, 256>>>();
    }

    pool_kernel<<<BSZ, 256>>>(w_out, (float*)d_out);
}

// round 16
// speedup vs baseline: 1.4870x; 1.0763x over previous
#include <cuda_runtime.h>
#include <math.h>
#include <stdint.h>

// Problem constants
#define BSZ   64
#define NTOK  1024
#define MCH   64
#define DCH   256       // 4*M
#define PDIM  64
#define RTOT  (BSZ*NTOK)   // 65536
#define HMAX  360
#define HPADMAX 384
#define EPSF  1e-5f
#define NBLK2 (RTOT/32)    // 2048 reglin blocks
#define NRB   (RTOT/16)    // 4096 row-blocks for packed h

// -------- scratch (static __device__ globals) --------
__device__ __align__(16) float g_h[(size_t)RTOT*DCH];
__device__ __align__(16) float g_y[(size_t)RTOT*DCH];
__device__ __align__(16) float g_hF[(size_t)NRB*16*2*32*4];   // packed tf32 h fragments
__device__ __align__(16) float g_q[(size_t)BSZ*HMAX*NTOK];
__device__ __align__(16) float g_kv[(size_t)BSZ*HMAX*NTOK];
__device__ __align__(16) float2 g_Ff[HMAX*NTOK];
// fragment-packed weights, 1-term tf32, k16 granularity
__device__ __align__(16) float g_WcF[16][3*HPADMAX/8][32][4];
__device__ __align__(16) float g_WoF[HPADMAX/16][32][32][4];
__device__ float g_part0[MCH*NBLK2];
__device__ float g_part1[MCH*NBLK2];
__device__ float g_scale0[MCH];
__device__ float g_scale1[MCH];

// ---------------------------------------------------------------------------
__device__ __forceinline__ void mma_tf32(float* c, const uint32_t* a, const uint32_t* b)
{
    asm volatile(
        "mma.sync.aligned.m16n8k8.row.col.f32.tf32.tf32.f32 "
        "{%0,%1,%2,%3}, {%4,%5,%6,%7}, {%8,%9}, {%0,%1,%2,%3};\n"
        : "+f"(c[0]), "+f"(c[1]), "+f"(c[2]), "+f"(c[3])
        : "r"(a[0]), "r"(a[1]), "r"(a[2]), "r"(a[3]), "r"(b[0]), "r"(b[1]));
}

__device__ __forceinline__ float tf32_rna_f(float x)
{
    uint32_t r;
    asm("cvt.rna.tf32.f32 %0, %1;" : "=r"(r) : "f"(x));
    return __uint_as_float(r);
}

__device__ __forceinline__ uint32_t sAddr(const void* p)
{
    return (uint32_t)__cvta_generic_to_shared(p);
}
__device__ __forceinline__ void cp16(uint32_t dst, const void* src)
{
    asm volatile("cp.async.cg.shared.global [%0], [%1], 16;\n" :: "r"(dst), "l"(src));
}
#define CP_COMMIT() asm volatile("cp.async.commit_group;\n")
#define CP_WAIT1()  asm volatile("cp.async.wait_group 1;\n")
#define CP_WAIT0()  asm volatile("cp.async.wait_group 0;\n")

__device__ __forceinline__ float2 cmul(float2 a, float2 b)
{ return make_float2(a.x*b.x - a.y*b.y, a.x*b.y + a.y*b.x); }
__device__ __forceinline__ float2 cadd(float2 a, float2 b){ return make_float2(a.x+b.x, a.y+b.y); }
__device__ __forceinline__ float2 csub(float2 a, float2 b){ return make_float2(a.x-b.x, a.y-b.y); }

// ---------------------------------------------------------------------------
// init h (fp32 residual stream — NEVER rounded)
// ---------------------------------------------------------------------------
__global__ void init_h_kernel(const float* __restrict__ x,
                              const float* __restrict__ tok_emb,
                              const float* __restrict__ Wf,
                              const float* __restrict__ wv)
{
    int n = blockIdx.x;
    int tid = threadIdx.x;   // 256
    __shared__ float f[PDIM];
    __shared__ float s0[MCH];
    if (tid < PDIM) {
        int p = tid;
        int j2 = p & ~1;
        float div = expf(-logf(10000.0f) * (float)j2 / (float)PDIM);
        float ang = (float)n * div;
        float pe = (p & 1) ? cosf(ang) : sinf(ang);
        int tt = (n == NTOK - 1) ? 2 : (n & 1);
        f[p] = pe + tok_emb[tt * PDIM + p];
    }
    __syncthreads();
    if (tid < MCH) {
        float acc = 0.f;
        #pragma unroll 8
        for (int p = 0; p < PDIM; p++) acc += f[p] * Wf[p * MCH + tid];
        s0[tid] = acc;
    }
    __syncthreads();
    int m = tid >> 2, r = tid & 3;
    float wvm = wv[m];
    float sv = s0[m];
    for (int b = 0; b < BSZ; b++) {
        float val;
        if (r == 0) val = sv;
        else        val = x[((size_t)b * NTOK + n) * 3 + (r - 1)] * wvm;
        g_h[((size_t)b * NTOK + n) * DCH + tid] = val;
    }
}

// ---------------------------------------------------------------------------
// repack h into tf32-rounded A-fragments (GEMM operand copy — rounding OK).
// One block per 16-row block; g_hF[RB][kb][grp][lane(g,t)][4]:
//   word0 = h[RB*16+g][kb*16+grp*8+t],     word1 = h[..g+8][same k],
//   word2 = h[..g  ][k+4],                 word3 = h[..g+8][k+4]
// ---------------------------------------------------------------------------
__global__ void __launch_bounds__(256) repack_h_kernel()
{
    __shared__ float hs[16][260];
    int tid = threadIdx.x;
    size_t RB = blockIdx.x;
    // load 16x256 = 1024 float4, 64 float4 per row
    #pragma unroll
    for (int i = 0; i < 4; i++) {
        int c = i * 256 + tid;           // float4 index over 1024
        int row = c >> 6, chq = c & 63;
        float4 v = *(const float4*)&g_h[(RB * 16 + row) * DCH + chq * 4];
        *(float4*)&hs[row][chq * 4] = v;
    }
    __syncthreads();
    #pragma unroll
    for (int i = 0; i < 4; i++) {
        int o = i * 256 + tid;           // output word index over 1024
        int kb = o >> 6, rem = o & 63;
        int grp = rem >> 5, lane = rem & 31;
        int g = lane >> 2, t = lane & 3;
        int kk = kb * 16 + grp * 8;
        float4 w;
        w.x = tf32_rna_f(hs[g    ][kk + t]);
        w.y = tf32_rna_f(hs[g + 8][kk + t]);
        w.z = tf32_rna_f(hs[g    ][kk + t + 4]);
        w.w = tf32_rna_f(hs[g + 8][kk + t + 4]);
        *(float4*)&g_hF[(RB * 4096) + (size_t)o * 4] = w;
    }
}

// ---------------------------------------------------------------------------
// weight pre-split (1-term RNA tf32). Column map over 3*HP:
//   c < HP  -> Wq column c
//   c >= HP -> j=c-HP; h=j>>1; even j -> Wk[h], odd j -> Wv[h]
// ---------------------------------------------------------------------------
template<int HP>
__global__ void presplit_cat(const float* __restrict__ Wq,
                             const float* __restrict__ Wk,
                             const float* __restrict__ Wv2, int H)
{
    int idx = blockIdx.x * 256 + threadIdx.x;   // over 256 * 3*HP
    int k = idx / (3 * HP), c = idx % (3 * HP);
    const float* W;
    int h;
    if (c < HP) { W = Wq; h = c; }
    else {
        int j = c - HP;
        h = j >> 1;
        W = (j & 1) ? Wv2 : Wk;
    }
    int kb = k >> 4, kk = k & 15;
    int grp = kk >> 3, kk8 = kk & 7;
    int t = kk8 & 3, pos = kk8 >> 2;
    int cb = c >> 3, lane = (c & 7) * 4 + t;
    float w = (h < H) ? W[(size_t)k * H + h] : 0.f;
    g_WcF[kb][cb][lane][grp * 2 + pos] = tf32_rna_f(w);
}

__global__ void presplit_wo(const float* __restrict__ Wo, int H)
{
    int idx = blockIdx.x * 256 + threadIdx.x;   // over HPADMAX*256
    int k = idx >> 8, n = idx & 255;
    int kb = k >> 4, kk = k & 15;
    int grp = kk >> 3, kk8 = kk & 7;
    int t = kk8 & 3, pos = kk8 >> 2;
    int cb = n >> 3, lane = (n & 7) * 4 + t;
    float w = (k < H) ? Wo[(size_t)k * DCH + n] : 0.f;
    g_WoF[kb][cb][lane][grp * 2 + pos] = tf32_rna_f(w);
}

// ---------------------------------------------------------------------------
// Merged qkv GEMM: C[R, 3*HP] = A[R,256] @ Wcat. Tile 128x128, kstep 16,
// 1-term tf32, A from packed g_hF (no cvt, LDS.128 fragments).
// 3-stage cp.async ring distance 2, loads after MMAs.
// ---------------------------------------------------------------------------
template<int HP>
__global__ void __launch_bounds__(256, 2) gemm_in(int H)
{
    __shared__ __align__(16) float shA[3][8 * 2 * 32 * 4];  // [rb][grp][lane][4]
    __shared__ __align__(16) float shB[3][16 * 32 * 4];

    int tid = threadIdx.x;
    int row0 = blockIdx.y * 128;
    int col0 = blockIdx.x * 128;        // over 3*HP
    int b = row0 >> 10;
    int nbase = row0 & (NTOK - 1);
    int cb0 = col0 >> 3;
    size_t RB0 = (size_t)blockIdx.y * 8;

    int wid = tid >> 5, lane = tid & 31;
    int g = lane >> 2, t = lane & 3;
    int wr = wid >> 2, wc = wid & 3;

    float acc[4][4][4] = {};

    #define IN_LOAD(kb, st)                                                   \
    {                                                                         \
        _Pragma("unroll")                                                     \
        for (int i = 0; i < 2; i++) {                                         \
            int c = i * 256 + tid;      /* over 512 words */                  \
            int rb = c >> 6, rem = c & 63;                                    \
            cp16(sAddr(&shA[st][(size_t)c * 4]),                              \
                 &g_hF[((RB0 + rb) * 16 + (kb)) * 256 + (size_t)rem * 4]);    \
        }                                                                     \
        _Pragma("unroll")                                                     \
        for (int i = 0; i < 2; i++) {                                         \
            int c = i * 256 + tid;                                            \
            int cb = c >> 5, ln = c & 31;                                     \
            cp16(sAddr(&shB[st][(cb * 32 + ln) * 4]),                         \
                 &g_WcF[kb][cb0 + cb][ln][0]);                                \
        }                                                                     \
        CP_COMMIT();                                                          \
    }

    IN_LOAD(0, 0);
    IN_LOAD(1, 1);

    for (int kb = 0; kb < 16; kb++) {
        if (kb == 15) { CP_WAIT0(); } else { CP_WAIT1(); }
        __syncthreads();
        int st = kb % 3;
        const float* A = shA[st];
        const float* B = shB[st];

        uint32_t ah[2][4][4];
        #pragma unroll
        for (int grp = 0; grp < 2; grp++) {
            #pragma unroll
            for (int mf = 0; mf < 4; mf++) {
                int rb = wr * 4 + mf;
                uint4 av = *(const uint4*)&A[((rb * 2 + grp) * 32 + lane) * 4];
                ah[grp][mf][0] = av.x;
                ah[grp][mf][1] = av.y;
                ah[grp][mf][2] = av.z;
                ah[grp][mf][3] = av.w;
            }
        }
        #pragma unroll
        for (int nf = 0; nf < 4; nf++) {
            int cb = wc * 4 + nf;
            float4 bf = *(const float4*)&B[(cb * 32 + lane) * 4];
            uint32_t b0[2] = {__float_as_uint(bf.x), __float_as_uint(bf.y)};
            uint32_t b1[2] = {__float_as_uint(bf.z), __float_as_uint(bf.w)};
            #pragma unroll
            for (int mf = 0; mf < 4; mf++) {
                mma_tf32(acc[mf][nf], ah[0][mf], b0);
                mma_tf32(acc[mf][nf], ah[1][mf], b1);
            }
        }
        if (kb + 2 < 16) {
            int kn = kb + 2;
            IN_LOAD(kn, kn % 3);
        }
    }
    #undef IN_LOAD

    if (col0 < HP) {
        // Q region (tiles never straddle: HP % 128 == 0)
        #pragma unroll
        for (int mf = 0; mf < 4; mf++) {
            #pragma unroll
            for (int nf = 0; nf < 4; nf++) {
                #pragma unroll
                for (int cc = 0; cc < 2; cc++) {
                    int col = col0 + wc * 32 + nf * 8 + t * 2 + cc;
                    if (col < H) {
                        size_t base = ((size_t)b * H + col) * NTOK + nbase + wr * 64 + mf * 16 + g;
                        g_q[base]     = acc[mf][nf][cc];
                        g_q[base + 8] = acc[mf][nf][cc + 2];
                    }
                }
            }
        }
    } else {
        // KV region: thread's two adjacent cols are (k_h, v_h) of same h
        #pragma unroll
        for (int mf = 0; mf < 4; mf++) {
            #pragma unroll
            for (int nf = 0; nf < 4; nf++) {
                int h = ((col0 - HP) >> 1) + wc * 16 + nf * 4 + t;
                if (h < H) {
                    size_t base = ((size_t)b * H + h) * NTOK + nbase + wr * 64 + mf * 16 + g;
                    g_kv[base]     = acc[mf][nf][0] * acc[mf][nf][1];
                    g_kv[base + 8] = acc[mf][nf][2] * acc[mf][nf][3];
                }
            }
        }
    }
}

// ---------------------------------------------------------------------------
// Wo GEMM + residual: g_h[R,256] += G[R,H] @ Wo[H,256].
// Tile 128x128, kstep 16, 1-term tf32, 3-stage ring, loads after MMAs.
// ---------------------------------------------------------------------------
__global__ void __launch_bounds__(256, 2) gemm_out(int H)
{
    __shared__ __align__(16) float shA[3][16 * 136];
    __shared__ __align__(16) float shB[3][16 * 32 * 4];

    int tid = threadIdx.x;
    int row0 = blockIdx.y * 128;
    int col0 = blockIdx.x * 128;
    int b = row0 >> 10;
    int nbase = row0 & (NTOK - 1);
    int cb0 = col0 >> 3;

    int wid = tid >> 5, lane = tid & 31;
    int g = lane >> 2, t = lane & 3;
    int wr = wid >> 2, wc = wid & 3;

    float acc[4][4][4] = {};

    int akk = tid >> 5, aseg = tid & 31;

    #define OUT_LOAD(kb, st)                                                     \
    {                                                                            \
        _Pragma("unroll")                                                        \
        for (int i = 0; i < 2; i++) {                                            \
            int k = akk + i * 8;                                                 \
            int krow = (kb) * 16 + k;                                            \
            if (krow > H - 1) krow = H - 1;                                      \
            cp16(sAddr(&shA[st][k * 136 + aseg * 4]),                            \
                 &g_q[((size_t)b * H + krow) * NTOK + nbase + aseg * 4]);        \
        }                                                                        \
        _Pragma("unroll")                                                        \
        for (int i = 0; i < 2; i++) {                                            \
            int c = i * 256 + tid;                                               \
            int cb = c >> 5, ln = c & 31;                                        \
            cp16(sAddr(&shB[st][(cb * 32 + ln) * 4]),                            \
                 &g_WoF[kb][cb0 + cb][ln][0]);                                   \
        }                                                                        \
        CP_COMMIT();                                                             \
    }

    int ksteps = (H + 15) >> 4;   // 23 or 10
    OUT_LOAD(0, 0);
    OUT_LOAD(1, 1);

    for (int kb = 0; kb < ksteps; kb++) {
        if (kb == ksteps - 1) { CP_WAIT0(); } else { CP_WAIT1(); }
        __syncthreads();
        int st = kb % 3;
        const float* A = shA[st];
        const float* B = shB[st];

        uint32_t ah[2][4][4];
        #pragma unroll
        for (int grp = 0; grp < 2; grp++) {
            int kk = grp * 8;
            #pragma unroll
            for (int mf = 0; mf < 4; mf++) {
                int rb = wr * 64 + mf * 16;
                ah[grp][mf][0] = __float_as_uint(A[(kk + t)     * 136 + rb + g]);
                ah[grp][mf][1] = __float_as_uint(A[(kk + t)     * 136 + rb + g + 8]);
                ah[grp][mf][2] = __float_as_uint(A[(kk + t + 4) * 136 + rb + g]);
                ah[grp][mf][3] = __float_as_uint(A[(kk + t + 4) * 136 + rb + g + 8]);
            }
        }
        #pragma unroll
        for (int nf = 0; nf < 4; nf++) {
            int cb = wc * 4 + nf;
            float4 bf = *(const float4*)&B[(cb * 32 + lane) * 4];
            uint32_t b0[2] = {__float_as_uint(bf.x), __float_as_uint(bf.y)};
            uint32_t b1[2] = {__float_as_uint(bf.z), __float_as_uint(bf.w)};
            #pragma unroll
            for (int mf = 0; mf < 4; mf++) {
                mma_tf32(acc[mf][nf], ah[0][mf], b0);
                mma_tf32(acc[mf][nf], ah[1][mf], b1);
            }
        }
        if (kb + 2 < ksteps) {
            int kn = kb + 2;
            OUT_LOAD(kn, kn % 3);
        }
    }
    #undef OUT_LOAD

    #pragma unroll
    for (int mf = 0; mf < 4; mf++) {
        #pragma unroll
        for (int nf = 0; nf < 4; nf++) {
            int col = col0 + wc * 32 + nf * 8 + t * 2;
            #pragma unroll
            for (int rr = 0; rr < 2; rr++) {
                int row = row0 + wr * 64 + mf * 16 + g + rr * 8;
                float2* hp = (float2*)&g_h[(size_t)row * DCH + col];
                float2 hv = *hp;
                hv.x += acc[mf][nf][rr * 2];
                hv.y += acc[mf][nf][rr * 2 + 1];
                *hp = hv;
            }
        }
    }
}

// ---------------------------------------------------------------------------
// 1024-pt radix-4 Stockham FFT, 256 worker lanes (ltid), ping-pong, result in y.
// ---------------------------------------------------------------------------
template<bool INV>
__device__ __forceinline__ void fft1024(float2* x, float2* y, const float2* tw, int ltid)
{
    float2* src = x;
    float2* dst = y;
    #pragma unroll
    for (int s = 0; s < 5; s++) {
        int m = 1 << (2 * s);
        float2 c0 = src[ltid];
        float2 c1 = src[ltid + 256];
        float2 c2 = src[ltid + 512];
        float2 c3 = src[ltid + 768];
        float2 t0 = cadd(c0, c2);
        float2 t1 = csub(c0, c2);
        float2 t2 = cadd(c1, c3);
        float2 d  = csub(c1, c3);
        float2 t3 = INV ? make_float2(-d.y, d.x) : make_float2(d.y, -d.x);
        int jm = ltid & ~(m - 1);
        float2 w1 = tw[jm];
        if (INV) w1.y = -w1.y;
        float2 w2 = cmul(w1, w1);
        float2 w3 = cmul(w2, w1);
        int base = ltid + 3 * jm;
        dst[base]         = cadd(t0, t2);
        dst[base + m]     = cmul(w1, cadd(t1, t3));
        dst[base + 2 * m] = cmul(w2, csub(t0, t2));
        dst[base + 3 * m] = cmul(w3, csub(t1, t3));
        __syncthreads();
        float2* tmp = src; src = dst; dst = tmp;
    }
}

__global__ void fft_filt_kernel(const float* __restrict__ filt, int H)
{
    int h = blockIdx.x;
    int tid = threadIdx.x;
    __shared__ float2 bufA[1024];
    __shared__ float2 bufB[1024];
    __shared__ float2 tw[256];
    {
        float ang = -6.283185307179586f * (float)tid / 1024.f;
        float sn, cs;
        sincosf(ang, &sn, &cs);
        tw[tid] = make_float2(cs, sn);
    }
    for (int n = tid; n < 1024; n += 256)
        bufA[n] = make_float2(filt[(size_t)n * H + h], 0.f);
    __syncthreads();
    fft1024<false>(bufA, bufB, tw, tid);
    for (int f = tid; f < 1024; f += 256)
        g_Ff[h * 1024 + f] = bufB[f];
}

// Packed-pair conv, TWO h per block (512 threads; fid selects FFT group).
__global__ void __launch_bounds__(512) conv_kernel(int H)
{
    int tid = threadIdx.x;
    int fid = tid >> 8;          // 0 or 1
    int ltid = tid & 255;
    int h = blockIdx.x * 2 + fid;
    int b0 = blockIdx.y * 2, b1 = b0 + 1;

    __shared__ float2 bufA[2][1024];
    __shared__ float2 bufB[2][1024];
    __shared__ float2 tw[256];
    if (fid == 0) {
        float ang = -6.283185307179586f * (float)ltid / 1024.f;
        float sn, cs;
        sincosf(ang, &sn, &cs);
        tw[ltid] = make_float2(cs, sn);
    }

    const float* kv0 = &g_kv[((size_t)b0 * H + h) * NTOK];
    const float* kv1 = &g_kv[((size_t)b1 * H + h) * NTOK];
    float* qp0 = &g_q[((size_t)b0 * H + h) * NTOK];
    float* qp1 = &g_q[((size_t)b1 * H + h) * NTOK];

    {
        float4 u = *(const float4*)&kv0[ltid * 4];
        float4 v = *(const float4*)&kv1[ltid * 4];
        bufA[fid][ltid * 4 + 0] = make_float2(u.x, v.x);
        bufA[fid][ltid * 4 + 1] = make_float2(u.y, v.y);
        bufA[fid][ltid * 4 + 2] = make_float2(u.z, v.z);
        bufA[fid][ltid * 4 + 3] = make_float2(u.w, v.w);
    }
    __syncthreads();
    fft1024<false>(bufA[fid], bufB[fid], tw, ltid);

    const float2* Fh = &g_Ff[h * 1024];
    for (int k = ltid; k <= 512; k += 256) {
        int nk = (1024 - k) & 1023;
        float2 Z = bufB[fid][k];
        float2 Y = bufB[fid][nk];
        float Ar = 0.5f * (Z.x + Y.x), Ai = 0.5f * (Z.y - Y.y);
        float Br = 0.5f * (Z.y + Y.y), Bi = 0.5f * (Y.x - Z.x);
        float2 F = Fh[k];
        float P1r = Ar * F.x - Ai * F.y, P1i = Ar * F.y + Ai * F.x;
        float P2r = Br * F.x - Bi * F.y, P2i = Br * F.y + Bi * F.x;
        bufA[fid][k] = make_float2(P1r - P2i, P1i + P2r);
        if (k != 0 && k != 512)
            bufA[fid][nk] = make_float2(P1r + P2i, -P1i + P2r);
    }
    __syncthreads();
    fft1024<true>(bufA[fid], bufB[fid], tw, ltid);

    const float inv = 1.f / 1024.f;
    {
        float4 q0 = *(const float4*)&qp0[ltid * 4];
        float4 q1 = *(const float4*)&qp1[ltid * 4];
        float2 c0 = bufB[fid][ltid * 4 + 0];
        float2 c1 = bufB[fid][ltid * 4 + 1];
        float2 c2 = bufB[fid][ltid * 4 + 2];
        float2 c3 = bufB[fid][ltid * 4 + 3];
        q0.x = tf32_rna_f(q0.x * c0.x * inv);
        q0.y = tf32_rna_f(q0.y * c1.x * inv);
        q0.z = tf32_rna_f(q0.z * c2.x * inv);
        q0.w = tf32_rna_f(q0.w * c3.x * inv);
        q1.x = tf32_rna_f(q1.x * c0.y * inv);
        q1.y = tf32_rna_f(q1.y * c1.y * inv);
        q1.z = tf32_rna_f(q1.z * c2.y * inv);
        q1.w = tf32_rna_f(q1.w * c3.y * inv);
        *(float4*)&qp0[ltid * 4] = q0;
        *(float4*)&qp1[ltid * 4] = q1;
    }
}

// ---------------------------------------------------------------------------
// reg_linear + BN partials: 32 tokens per block (fp32 FMA — precision-critical)
// ---------------------------------------------------------------------------
__global__ void __launch_bounds__(256) reglin_kernel(const float* __restrict__ Wm0,
                                                     const float* __restrict__ Wm1)
{
    __shared__ float W0[64 * 64];
    __shared__ float W1[64 * 64];
    __shared__ __align__(16) float hs[8 * 256];
    __shared__ float red0[256], red1[256];
    int tid = threadIdx.x;
    int row0 = blockIdx.x * 32;
    for (int i = tid; i < 4096; i += 256) { W0[i] = Wm0[i]; W1[i] = Wm1[i]; }
    int k = tid & 63, grp = tid >> 6;
    float ls0 = 0.f, ls1 = 0.f;
    for (int batch = 0; batch < 4; batch++) {
        __syncthreads();
        for (int i = tid; i < 2048; i += 256)
            hs[i] = g_h[(size_t)(row0 + batch * 8) * DCH + i];
        __syncthreads();
        #pragma unroll
        for (int tt = 0; tt < 2; tt++) {
            int t = grp * 2 + tt;
            const float* hr = &hs[t * 256];
            float s = 0.f, v0 = 0.f, v1 = 0.f, v2 = 0.f;
            #pragma unroll 8
            for (int m = 0; m < 64; m++) {
                float4 hv = *(const float4*)&hr[m * 4];
                float w0 = W0[m * 64 + k];
                float w1 = W1[m * 64 + k];
                s  += hv.x * w0;
                v0 += hv.y * w1;
                v1 += hv.z * w1;
                v2 += hv.w * w1;
            }
            *(float4*)&g_y[(size_t)(row0 + batch * 8 + t) * DCH + k * 4] = make_float4(s, v0, v1, v2);
            ls0 += s * s;
            ls1 += v0 * v0 + v1 * v1 + v2 * v2;
        }
    }
    red0[tid] = ls0; red1[tid] = ls1;
    __syncthreads();
    if (grp == 0) {
        float t0 = red0[k] + red0[64 + k] + red0[128 + k] + red0[192 + k];
        float t1 = red1[k] + red1[64 + k] + red1[128 + k] + red1[192 + k];
        g_part0[k * NBLK2 + blockIdx.x] = t0;
        g_part1[k * NBLK2 + blockIdx.x] = t1;
    }
}

__global__ void scale_red_kernel(const float* __restrict__ g0, const float* __restrict__ g1)
{
    int c = blockIdx.x;          // 0..127
    int ch = c & 63;
    const float* src = (c < 64) ? &g_part0[(size_t)ch * NBLK2] : &g_part1[(size_t)ch * NBLK2];
    int tid = threadIdx.x;
    float s = 0.f;
    for (int i = tid; i < NBLK2; i += 256) s += src[i];
    __shared__ float red[256];
    red[tid] = s;
    __syncthreads();
    for (int st = 128; st; st >>= 1) {
        if (tid < st) red[tid] += red[tid + st];
        __syncthreads();
    }
    if (tid == 0) {
        float norm = sqrtf(red[0] / (float)RTOT + EPSF);
        if (c < 64) g_scale0[ch] = g0[ch] / norm;
        else        g_scale1[ch] = g1[ch] / norm;
    }
}

// BN + act + residual (fp32 residual stream — never rounded)
__global__ void actres_kernel()
{
    size_t idx = (size_t)blockIdx.x * 256 + threadIdx.x;
    int m = (int)(idx & 63);
    float4 yv = *(float4*)&g_y[idx * 4];
    float s  = yv.x * g_scale0[m];
    float sc = g_scale1[m];
    float v0 = yv.y * sc, v1 = yv.z * sc, v2 = yv.w * sc;
    float sg  = 1.f / (1.f + __expf(-fabsf(s)));
    float vn  = sqrtf(v0 * v0 + v1 * v1 + v2 * v2 + EPSF);
    float sgv = 1.f / (1.f + __expf(-vn));
    float4* hp = (float4*)&g_h[idx * 4];
    float4 hv = *hp;
    hv.x += s * sg;
    hv.y += v0 * sgv;
    hv.z += v1 * sgv;
    hv.w += v2 * sgv;
    *hp = hv;
}

__global__ void pool_kernel(const float* __restrict__ w_out, float* __restrict__ out)
{
    int b = blockIdx.x;
    int tid = threadIdx.x;
    __shared__ float wsh[64];
    if (tid < 64) wsh[tid] = w_out[tid];
    __syncthreads();
    float a0 = 0.f, a1 = 0.f, a2 = 0.f;
    for (int n = tid; n < NTOK; n += 256) {
        const float* hr = &g_h[((size_t)b * NTOK + n) * DCH];
        #pragma unroll 8
        for (int m = 0; m < 64; m++) {
            float w = wsh[m];
            float4 hv = *(const float4*)&hr[m * 4];
            a0 += hv.y * w;
            a1 += hv.z * w;
            a2 += hv.w * w;
        }
    }
    __shared__ float r0[256], r1[256], r2[256];
    r0[tid] = a0; r1[tid] = a1; r2[tid] = a2;
    __syncthreads();
    for (int st = 128; st; st >>= 1) {
        if (tid < st) { r0[tid] += r0[tid + st]; r1[tid] += r1[tid + st]; r2[tid] += r2[tid + st]; }
        __syncthreads();
    }
    if (tid == 0) {
        out[b * 3 + 0] = r0[0] / (float)NTOK;
        out[b * 3 + 1] = r1[0] / (float)NTOK;
        out[b * 3 + 2] = r2[0] / (float)NTOK;
    }
}

// ---------------------------------------------------------------------------
extern "C" void kernel_launch(void* const* d_in, const int* in_sizes, int n_in,
                              void* d_out, int out_size)
{
    (void)in_sizes; (void)n_in; (void)out_size;
    const float* x       = (const float*)d_in[0];
    const float* tok_emb = (const float*)d_in[1];
    const float* Wf      = (const float*)d_in[2];
    const float* wv      = (const float*)d_in[3];
    const float* w_out   = (const float*)d_in[4];
    const int Hs[3] = {360, 360, 160};

    init_h_kernel<<<NTOK, 256>>>(x, tok_emb, Wf, wv);
    repack_h_kernel<<<NRB, 256>>>();

    for (int L = 0; L < 3; L++) {
        int base = 5 + L * 9;
        const float* Wq   = (const float*)d_in[base + 0];
        const float* Wk   = (const float*)d_in[base + 1];
        const float* Wvw  = (const float*)d_in[base + 2];
        const float* filt = (const float*)d_in[base + 3];
        const float* Wo   = (const float*)d_in[base + 4];
        const float* Wm0  = (const float*)d_in[base + 5];
        const float* Wm1  = (const float*)d_in[base + 6];
        const float* g0   = (const float*)d_in[base + 7];
        const float* g1   = (const float*)d_in[base + 8];
        int H = Hs[L];

        if (H > 256) {
            presplit_cat<384><<<256 * 3 * 384 / 256, 256>>>(Wq, Wk, Wvw, H);
            gemm_in<384><<<dim3(3 * 384 / 128, RTOT / 128), 256>>>(H);
        } else {
            presplit_cat<256><<<256 * 3 * 256 / 256, 256>>>(Wq, Wk, Wvw, H);
            gemm_in<256><<<dim3(3 * 256 / 128, RTOT / 128), 256>>>(H);
        }
        presplit_wo<<<HPADMAX * DCH / 256, 256>>>(Wo, H);
        fft_filt_kernel<<<H, 256>>>(filt, H);
        conv_kernel<<<dim3(H / 2, BSZ / 2), 512>>>(H);
        gemm_out<<<dim3(DCH / 128, RTOT / 128), 256>>>(H);
        reglin_kernel<<<NBLK2, 256>>>(Wm0, Wm1);
        scale_red_kernel<<<128, 256>>>(g0, g1);
        actres_kernel<<<RTOT * 64 / 256, 256>>>();
        if (L < 2) repack_h_kernel<<<NRB, 256>>>();
    }

    pool_kernel<<<BSZ, 256>>>(w_out, (float*)d_out);
}